// round 13
// baseline (speedup 1.0000x reference)
#include <cuda_runtime.h>
#include <cuda_bf16.h>
#include <math.h>
#include <stdint.h>

#define BATCH 8
#define NTOK 3136
#define MROWS (BATCH * NTOK)   // 25088
#define ASCALE 0.0625f
#define PLP 49

// ---------------- scratch ---------------------------------------------------
__device__ __align__(128) float g_q[MROWS * 256];          // (B,NH,N,HD)
__device__ __align__(128) float g_kv[MROWS * 512];         // (B,N,512)
__device__ __align__(128) float g_xsr[MROWS * 256];
__device__ __align__(128) float g_xp[BATCH * PLP * 256];
__device__ __align__(128) float g_kvp[BATCH * PLP * 512];
__device__ __align__(128) float g_bcat[1024];
__device__ __align__(128) __nv_bfloat16 g_xhi[MROWS * 256];
__device__ __align__(128) __nv_bfloat16 g_xlo[MROWS * 256];
__device__ __align__(128) __nv_bfloat16 g_wthi[1024 * 256];   // W^T (N x K)
__device__ __align__(128) __nv_bfloat16 g_wtlo[1024 * 256];
__device__ __align__(128) __nv_bfloat16 g_wphi[256 * 256];    // Wproj^T
__device__ __align__(128) __nv_bfloat16 g_wplo[256 * 256];
__device__ __align__(128) __nv_bfloat16 g_ohi[MROWS * 256];
__device__ __align__(128) __nv_bfloat16 g_olo[MROWS * 256];

// ---------------- helpers ----------------------------------------------------
__device__ __forceinline__ uint32_t s2u(const void* p) {
    uint32_t a;
    asm("{ .reg .u64 t; cvta.to.shared.u64 t, %1; cvt.u32.u64 %0, t; }" : "=r"(a) : "l"(p));
    return a;
}
__device__ __forceinline__ void cp_async16(uint32_t saddr, const void* gaddr) {
    asm volatile("cp.async.cg.shared.global [%0], [%1], 16;" :: "r"(saddr), "l"(gaddr));
}
__device__ __forceinline__ void cp_commit() {
    asm volatile("cp.async.commit_group;");
}
__device__ __forceinline__ void ldsm4(uint32_t r[4], uint32_t addr) {
    asm volatile("ldmatrix.sync.aligned.m8n8.x4.shared.b16 {%0,%1,%2,%3}, [%4];"
                 : "=r"(r[0]), "=r"(r[1]), "=r"(r[2]), "=r"(r[3]) : "r"(addr));
}
__device__ __forceinline__ void hmma(float c[4], const uint32_t a[4],
                                     uint32_t b0, uint32_t b1) {
    asm volatile(
        "mma.sync.aligned.m16n8k16.row.col.f32.bf16.bf16.f32 "
        "{%0,%1,%2,%3}, {%4,%5,%6,%7}, {%8,%9}, {%0,%1,%2,%3};"
        : "+f"(c[0]), "+f"(c[1]), "+f"(c[2]), "+f"(c[3])
        : "r"(a[0]), "r"(a[1]), "r"(a[2]), "r"(a[3]), "r"(b0), "r"(b1));
}

// ---------------- prep kernels ------------------------------------------------
__global__ void split_x(const float* __restrict__ x) {
    int i = blockIdx.x * blockDim.x + threadIdx.x;
    int stride = gridDim.x * blockDim.x;
    const int TOT4 = (MROWS * 256) / 4;
    for (; i < TOT4; i += stride) {
        float4 v = ((const float4*)x)[i];
        __nv_bfloat16 h0 = __float2bfloat16(v.x);
        __nv_bfloat16 h1 = __float2bfloat16(v.y);
        __nv_bfloat16 h2 = __float2bfloat16(v.z);
        __nv_bfloat16 h3 = __float2bfloat16(v.w);
        __nv_bfloat162 hi0(h0, h1), hi1(h2, h3);
        __nv_bfloat162 lo0(__float2bfloat16(v.x - __bfloat162float(h0)),
                           __float2bfloat16(v.y - __bfloat162float(h1)));
        __nv_bfloat162 lo1(__float2bfloat16(v.z - __bfloat162float(h2)),
                           __float2bfloat16(v.w - __bfloat162float(h3)));
        ((uint32_t*)g_xhi)[i * 2 + 0] = *(uint32_t*)&hi0;
        ((uint32_t*)g_xhi)[i * 2 + 1] = *(uint32_t*)&hi1;
        ((uint32_t*)g_xlo)[i * 2 + 0] = *(uint32_t*)&lo0;
        ((uint32_t*)g_xlo)[i * 2 + 1] = *(uint32_t*)&lo1;
    }
}

__global__ void pack_w(const float* __restrict__ Wq, const float* __restrict__ Wkv,
                       const float* __restrict__ Wsr, const float* __restrict__ Wproj,
                       const float* __restrict__ bq, const float* __restrict__ bkv,
                       const float* __restrict__ bsr, const float* __restrict__ qe) {
    int t = blockIdx.x * blockDim.x + threadIdx.x;
    int stride = gridDim.x * blockDim.x;
    if (t < 1024)
        g_bcat[t] = (t < 256) ? (bq[t] + qe[t]) : (t < 768 ? bkv[t - 256] : bsr[t - 768]);
    const int TOT = 1024 * 256 + 256 * 256;
    for (int idx = t; idx < TOT; idx += stride) {
        float w;
        if (idx < 1024 * 256) {
            int c = idx >> 8, k = idx & 255;
            if (c < 256)      w = Wq[k * 256 + c];
            else if (c < 768) w = Wkv[k * 512 + (c - 256)];
            else              w = Wsr[k * 256 + (c - 768)];
            __nv_bfloat16 h = __float2bfloat16(w);
            g_wthi[idx] = h;
            g_wtlo[idx] = __float2bfloat16(w - __bfloat162float(h));
        } else {
            int j = idx - 1024 * 256;
            int c = j >> 8, k = j & 255;
            w = Wproj[k * 256 + c];
            __nv_bfloat16 h = __float2bfloat16(w);
            g_wphi[j] = h;
            g_wplo[j] = __float2bfloat16(w - __bfloat162float(h));
        }
    }
}

// ---------------- HMMA bf16x3 GEMM: fused stage + swizzle, K=32 chunks --------
#define STGF 32768
#define T_AL 8192
#define T_BH 16384
#define T_BL 24576
__global__ __launch_bounds__(256, 2)
void gemm_mma(const __nv_bfloat16* __restrict__ Ah, const __nv_bfloat16* __restrict__ Al,
              const __nv_bfloat16* __restrict__ Bh, const __nv_bfloat16* __restrict__ Bl,
              const float* __restrict__ bias, float* __restrict__ Cout, int mode) {
    extern __shared__ __align__(128) uint8_t smem[];
    const int t = threadIdx.x, w = t >> 5, lane = t & 31;
    const int bm = blockIdx.y * 128, bn = blockIdx.x * 128;
    const int wm = (w >> 2) * 64, wn = (w & 3) * 32;
    const uint32_t sbase = s2u(smem);

    float c[4][4][4];
#pragma unroll
    for (int i = 0; i < 4; i++)
#pragma unroll
        for (int j = 0; j < 4; j++)
#pragma unroll
            for (int k = 0; k < 4; k++) c[i][j][k] = 0.f;

    uint32_t aRow[4], bRow[2];
#pragma unroll
    for (int mt = 0; mt < 4; mt++)
        aRow[mt] = (uint32_t)((wm + mt * 16 + (lane & 15)) * 64);
    {
        int nr = wn + (lane >> 4) * 8 + (lane & 7);
        bRow[0] = (uint32_t)(nr * 64);
        bRow[1] = (uint32_t)((nr + 16) * 64);
    }
    const uint32_t aSw = (uint32_t)(((lane & 15) >> 1) & 3);
    const uint32_t bSw = (uint32_t)(((lane & 7) >> 1) & 3);
    const uint32_t cA = (uint32_t)(lane >> 4);
    const uint32_t cB = (uint32_t)((lane >> 3) & 1);

    const int r0 = t >> 2, cc = t & 3;
    const uint32_t csw = (uint32_t)((cc ^ ((r0 >> 1) & 3)) << 4);
    const size_t aG = (size_t)(bm + r0) * 256 + cc * 8;
    const size_t bG = (size_t)(bn + r0) * 256 + cc * 8;
    const uint32_t sd0 = (uint32_t)(r0 * 64) + csw;
    const uint32_t sd1 = sd0 + 64 * 64;

#define ISSUE(IT)                                                     \
    do {                                                              \
        uint32_t _so = sbase + ((IT) % 3) * STGF;                     \
        int _ko = (IT) * 32;                                          \
        cp_async16(_so + sd0,        Ah + aG + _ko);                  \
        cp_async16(_so + sd1,        Ah + aG + 64 * 256 + _ko);       \
        cp_async16(_so + T_AL + sd0, Al + aG + _ko);                  \
        cp_async16(_so + T_AL + sd1, Al + aG + 64 * 256 + _ko);       \
        cp_async16(_so + T_BH + sd0, Bh + bG + _ko);                  \
        cp_async16(_so + T_BH + sd1, Bh + bG + 64 * 256 + _ko);       \
        cp_async16(_so + T_BL + sd0, Bl + bG + _ko);                  \
        cp_async16(_so + T_BL + sd1, Bl + bG + 64 * 256 + _ko);       \
        cp_commit();                                                  \
    } while (0)

    ISSUE(0); ISSUE(1);

#pragma unroll 1
    for (int it = 0; it < 8; it++) {
        if (it < 7) asm volatile("cp.async.wait_group 1;");
        else        asm volatile("cp.async.wait_group 0;");
        __syncthreads();
        if (it + 2 < 8) ISSUE(it + 2);

        uint32_t so = sbase + (it % 3) * STGF;
#pragma unroll
        for (int ks = 0; ks < 2; ks++) {
            uint32_t swA = ((cA + 2 * ks) ^ aSw) << 4;
            uint32_t swB = ((cB + 2 * ks) ^ bSw) << 4;
            uint32_t a[4][4], bh[2][4], bl[2][4];
#pragma unroll
            for (int np = 0; np < 2; np++) {
                ldsm4(bh[np], so + T_BH + bRow[np] + swB);
                ldsm4(bl[np], so + T_BL + bRow[np] + swB);
            }
#pragma unroll
            for (int mt = 0; mt < 4; mt++) ldsm4(a[mt], so + aRow[mt] + swA);
#pragma unroll
            for (int mt = 0; mt < 4; mt++)
#pragma unroll
                for (int nt = 0; nt < 4; nt++)
                    hmma(c[mt][nt], a[mt], bh[nt >> 1][(nt & 1) * 2],
                         bh[nt >> 1][(nt & 1) * 2 + 1]);
#pragma unroll
            for (int mt = 0; mt < 4; mt++)
#pragma unroll
                for (int nt = 0; nt < 4; nt++)
                    hmma(c[mt][nt], a[mt], bl[nt >> 1][(nt & 1) * 2],
                         bl[nt >> 1][(nt & 1) * 2 + 1]);
#pragma unroll
            for (int mt = 0; mt < 4; mt++) ldsm4(a[mt], so + T_AL + aRow[mt] + swA);
#pragma unroll
            for (int mt = 0; mt < 4; mt++)
#pragma unroll
                for (int nt = 0; nt < 4; nt++)
                    hmma(c[mt][nt], a[mt], bh[nt >> 1][(nt & 1) * 2],
                         bh[nt >> 1][(nt & 1) * 2 + 1]);
        }
    }
#undef ISSUE

    const int g = lane >> 2, tq = lane & 3;
#pragma unroll
    for (int mt = 0; mt < 4; mt++) {
#pragma unroll
        for (int rs = 0; rs < 2; rs++) {
            int row = bm + wm + mt * 16 + g + rs * 8;
            int b = row / NTOK, n = row - b * NTOK;
#pragma unroll
            for (int nt = 0; nt < 4; nt++) {
#pragma unroll
                for (int cs = 0; cs < 2; cs++) {
                    int col = bn + wn + nt * 8 + tq * 2 + cs;
                    float v = c[mt][nt][rs * 2 + cs] + bias[col];
                    if (mode == 0) {
                        if (col < 256) {
                            int h = col >> 5, d = col & 31;
                            g_q[(((size_t)b * 8 + h) * NTOK + n) * 32 + d] = v;
                        } else if (col < 768) {
                            g_kv[((size_t)b * NTOK + n) * 512 + (col - 256)] = v;
                        } else {
                            float gl = 0.5f * v * (1.f + erff(v * 0.70710678118654752f));
                            g_xsr[((size_t)b * NTOK + n) * 256 + (col - 768)] = gl;
                        }
                    } else {
                        Cout[(size_t)row * 256 + col] = v;
                    }
                }
            }
        }
    }
}

// ---------------- pool (8x8 mean) + layernorm, warp-shuffle reductions --------
__global__ void pool_ln(const float* __restrict__ ln_g, const float* __restrict__ ln_b) {
    int bp = blockIdx.x;
    int b = bp / PLP, p = bp % PLP;
    int ph = p / 7, pw = p % 7;
    int c = threadIdx.x;
    int wid = c >> 5, lane = c & 31;
    float s = 0.f;
    const float* base = g_xsr + (size_t)b * NTOK * 256 + c;
#pragma unroll
    for (int ii = 0; ii < 8; ii++)
#pragma unroll
        for (int jj = 0; jj < 8; jj++)
            s += base[(size_t)((ph * 8 + ii) * 56 + pw * 8 + jj) * 256];
    s *= (1.f / 64.f);

    __shared__ float wred[8];
    __shared__ float stat[2];
    float v = s;
#pragma unroll
    for (int o = 16; o; o >>= 1) v += __shfl_xor_sync(0xffffffffu, v, o);
    if (lane == 0) wred[wid] = v;
    __syncthreads();
    if (c == 0) {
        float tot = 0.f;
#pragma unroll
        for (int u = 0; u < 8; u++) tot += wred[u];
        stat[0] = tot * (1.f / 256.f);
    }
    __syncthreads();
    float mu = stat[0];
    float d = s - mu;
    v = d * d;
#pragma unroll
    for (int o = 16; o; o >>= 1) v += __shfl_xor_sync(0xffffffffu, v, o);
    if (lane == 0) wred[wid] = v;
    __syncthreads();
    if (c == 0) {
        float tot = 0.f;
#pragma unroll
        for (int u = 0; u < 8; u++) tot += wred[u];
        stat[1] = tot * (1.f / 256.f);
    }
    __syncthreads();
    float var = stat[1];
    g_xp[(size_t)bp * 256 + c] = d * rsqrtf(var + 1e-5f) * ln_g[c] + ln_b[c];
}

// ---------------- small kvp GEMM (392 x 512 x 256), 4 rows/block -------------
__global__ __launch_bounds__(256)
void kvp_gemm(const float* __restrict__ Wkv, const float* __restrict__ bkv) {
    __shared__ float sx[4][256];
    int t = threadIdx.x;
    int r0 = blockIdx.x * 4;
#pragma unroll
    for (int r = 0; r < 4; r++) sx[r][t] = g_xp[(size_t)(r0 + r) * 256 + t];
    __syncthreads();
    int c0 = t * 2;
    float a0[4], a1[4];
#pragma unroll
    for (int r = 0; r < 4; r++) { a0[r] = 0.f; a1[r] = 0.f; }
#pragma unroll 4
    for (int k = 0; k < 256; k++) {
        float2 w = *(const float2*)(Wkv + (size_t)k * 512 + c0);
#pragma unroll
        for (int r = 0; r < 4; r++) {
            float xv = sx[r][k];
            a0[r] = fmaf(xv, w.x, a0[r]);
            a1[r] = fmaf(xv, w.y, a1[r]);
        }
    }
    float b0 = bkv[c0], b1 = bkv[c0 + 1];
#pragma unroll
    for (int r = 0; r < 4; r++) {
        g_kvp[(size_t)(r0 + r) * 512 + c0]     = a0[r] + b0;
        g_kvp[(size_t)(r0 + r) * 512 + c0 + 1] = a1[r] + b1;
    }
}

// ---------------- attention v4: 2 tokens/thread, d-split, streaming -----------
// smem: sk[32][349], sv[32][349] (6 kv-rows x 58 slots d-major, ODD stride),
//       skp[49][32], svp[49][32], sLT[9][32], sb[67]
// only sv is zero-initialized (value side must be exact zero at masked slots);
// sk garbage at pads/OOB is discarded by the validity predicates.
#define SK_OFF   0
#define SV_OFF   11168
#define SKP_OFF  22336
#define SVP_OFF  23904
#define SLT_OFF  25472
#define SB_OFF   25760
#define ATTN_SMEM_FLOATS 25828

__global__ __launch_bounds__(256, 2)
void attn4(const float* __restrict__ pbp, const float* __restrict__ pbl,
           const float* __restrict__ LT, const float* __restrict__ lb) {
    extern __shared__ __align__(16) float sm[];
    float* sk  = sm + SK_OFF;
    float* sv  = sm + SV_OFF;
    float* skp = sm + SKP_OFF;
    float* svp = sm + SVP_OFF;
    float* sLT = sm + SLT_OFF;
    float* sb  = sm + SB_OFF;

    const int t = threadIdx.x, w = t >> 5, lane = t & 31;
    const int h  = blockIdx.y;
    const int b  = blockIdx.z;
    const int i0 = blockIdx.x * 4;

    // zero ONLY the value staging
    {
        float4* z = (float4*)sv;
        for (int idx = t; idx < 11168 / 4; idx += 256)
            z[idx] = make_float4(0.f, 0.f, 0.f, 0.f);
    }
    if (t < 49)       sb[t] = pbp[h * 49 + t];
    else if (t < 58)  sb[t] = pbl[h * 9 + (t - 49)];
    else if (t < 67)  sb[t] = lb[h * 9 + (t - 58)];
    __syncthreads();

    // stage local k/v rows i0-1 .. i0+4 (6 rows), d-major stride 349
    for (int tok = t; tok < 336; tok += 256) {
        int ri = tok / 56, cc = tok - ri * 56;
        int gr = i0 - 1 + ri;
        if ((unsigned)gr < 56u) {
            int n = gr * 56 + cc;
            const float4* kg = (const float4*)(g_kv + ((size_t)(b * NTOK + n) * 512 + h * 32));
            int sbs = ri * 58 + cc + 1;
#pragma unroll
            for (int u = 0; u < 8; u++) {
                float4 kk = kg[u];
                float4 vv = kg[64 + u];
                sk[(u * 4 + 0) * 349 + sbs] = kk.x;
                sk[(u * 4 + 1) * 349 + sbs] = kk.y;
                sk[(u * 4 + 2) * 349 + sbs] = kk.z;
                sk[(u * 4 + 3) * 349 + sbs] = kk.w;
                sv[(u * 4 + 0) * 349 + sbs] = vv.x;
                sv[(u * 4 + 1) * 349 + sbs] = vv.y;
                sv[(u * 4 + 2) * 349 + sbs] = vv.z;
                sv[(u * 4 + 3) * 349 + sbs] = vv.w;
            }
        }
    }
    for (int idx = t; idx < 49 * 8; idx += 256) {
        int p = idx >> 3, d4 = idx & 7;
        const float4* src = (const float4*)(g_kvp + ((size_t)(b * PLP + p) * 512 + h * 32));
        *(float4*)(skp + p * 32 + d4 * 4) = src[d4];
        *(float4*)(svp + p * 32 + d4 * 4) = src[64 + d4];
    }
    for (int idx = t; idx < 288; idx += 256) {
        int d = idx / 9, l = idx - d * 9;
        sLT[l * 32 + d] = LT[(h * 32 + d) * 9 + l];
    }
    __syncthreads();

    // thread mapping: warp = 14 j-cols x (2 rows x 2 d-halves)
    const int rp2 = w >> 2;               // 0..1  -> rows i0+2*rp2, +1
    const int jt  = w & 3;                // 0..3
    const int jj  = lane >> 1;            // 0..15
    const int dh  = lane & 1;
    const bool act = jj < 14;
    const int j  = jt * 14 + (act ? jj : 0);
    const int iA = i0 + rp2 * 2;
    const int nA = iA * 56 + j;
    const int dbase = dh * 16;

    float qA[16], qB[16];
    {
        const float4* qsA = (const float4*)(g_q + ((((size_t)b * 8 + h) * NTOK + nA) * 32 + dbase));
        const float4* qsB = (const float4*)(g_q + ((((size_t)b * 8 + h) * NTOK + nA + 56) * 32 + dbase));
#pragma unroll
        for (int u = 0; u < 4; u++) {
            float4 a = qsA[u], c = qsB[u];
            qA[u * 4 + 0] = a.x; qA[u * 4 + 1] = a.y; qA[u * 4 + 2] = a.z; qA[u * 4 + 3] = a.w;
            qB[u * 4 + 0] = c.x; qB[u * 4 + 1] = c.y; qB[u * 4 + 2] = c.z; qB[u * 4 + 3] = c.w;
        }
    }

    float eA9[9], eB9[9];
    float SA = 0.f, SB = 0.f;

    // phase 1: local logits (store e's, accumulate S)
#pragma unroll
    for (int l = 0; l < 9; l++) {
        int di = l / 3, dj = l - di * 3;
        int sA = (rp2 * 2 + di) * 58 + j + dj;   // token A slot
        int sB = sA + 58;                         // token B slot (row +1)
        float dA = 0.f, dB = 0.f;
#pragma unroll
        for (int d = 0; d < 16; d++) {
            dA = fmaf(qA[d], sk[(dbase + d) * 349 + sA], dA);
            dB = fmaf(qB[d], sk[(dbase + d) * 349 + sB], dB);
        }
        dA += __shfl_xor_sync(0xffffffffu, dA, 1);
        dB += __shfl_xor_sync(0xffffffffu, dB, 1);
        bool vA = act && ((unsigned)(iA + di - 1) < 56u) && ((unsigned)(j + dj - 1) < 56u);
        bool vB = act && ((unsigned)(iA + di) < 56u) && ((unsigned)(j + dj - 1) < 56u);
        float eA = vA ? __expf(dA * ASCALE + sb[49 + l]) : 0.f;
        float eB = vB ? __expf(dB * ASCALE + sb[49 + l]) : 0.f;
        eA9[l] = eA; eB9[l] = eB;
        SA += eA; SB += eB;
    }

    // phase 2: pooled streaming (dots + accumulate e*v)
    float oA[16], oB[16];
#pragma unroll
    for (int d = 0; d < 16; d++) { oA[d] = 0.f; oB[d] = 0.f; }
#pragma unroll 7
    for (int p = 0; p < 49; p++) {
        const float4* kp4 = (const float4*)(skp + p * 32 + dbase);
        float dA = 0.f, dB = 0.f;
#pragma unroll
        for (int u = 0; u < 4; u++) {
            float4 kk = kp4[u];
            dA = fmaf(qA[u * 4 + 0], kk.x, dA); dA = fmaf(qA[u * 4 + 1], kk.y, dA);
            dA = fmaf(qA[u * 4 + 2], kk.z, dA); dA = fmaf(qA[u * 4 + 3], kk.w, dA);
            dB = fmaf(qB[u * 4 + 0], kk.x, dB); dB = fmaf(qB[u * 4 + 1], kk.y, dB);
            dB = fmaf(qB[u * 4 + 2], kk.z, dB); dB = fmaf(qB[u * 4 + 3], kk.w, dB);
        }
        dA += __shfl_xor_sync(0xffffffffu, dA, 1);
        dB += __shfl_xor_sync(0xffffffffu, dB, 1);
        float eA = __expf(dA * ASCALE + sb[p]);
        float eB = __expf(dB * ASCALE + sb[p]);
        SA += eA; SB += eB;
        const float4* vp4 = (const float4*)(svp + p * 32 + dbase);
#pragma unroll
        for (int u = 0; u < 4; u++) {
            float4 vv = vp4[u];
            oA[u * 4 + 0] = fmaf(eA, vv.x, oA[u * 4 + 0]);
            oA[u * 4 + 1] = fmaf(eA, vv.y, oA[u * 4 + 1]);
            oA[u * 4 + 2] = fmaf(eA, vv.z, oA[u * 4 + 2]);
            oA[u * 4 + 3] = fmaf(eA, vv.w, oA[u * 4 + 3]);
            oB[u * 4 + 0] = fmaf(eB, vv.x, oB[u * 4 + 0]);
            oB[u * 4 + 1] = fmaf(eB, vv.y, oB[u * 4 + 1]);
            oB[u * 4 + 2] = fmaf(eB, vv.z, oB[u * 4 + 2]);
            oB[u * 4 + 3] = fmaf(eB, vv.w, oB[u * 4 + 3]);
        }
    }

    // phase 3: scale pooled accumulations by 1/S
    float invA = 1.f / SA, invB = 1.f / SB;
#pragma unroll
    for (int d = 0; d < 16; d++) { oA[d] *= invA; oB[d] *= invB; }

    // phase 4: local values with full weights (e/S + A9); LT dots computed here
#pragma unroll
    for (int l = 0; l < 9; l++) {
        int di = l / 3, dj = l - di * 3;
        int sA = (rp2 * 2 + di) * 58 + j + dj;
        int sB = sA + 58;
        const float4* lt4 = (const float4*)(sLT + l * 32 + dbase);
        float ltA = 0.f, ltB = 0.f;
#pragma unroll
        for (int u = 0; u < 4; u++) {
            float4 kk = lt4[u];
            ltA = fmaf(qA[u * 4 + 0], kk.x, ltA); ltA = fmaf(qA[u * 4 + 1], kk.y, ltA);
            ltA = fmaf(qA[u * 4 + 2], kk.z, ltA); ltA = fmaf(qA[u * 4 + 3], kk.w, ltA);
            ltB = fmaf(qB[u * 4 + 0], kk.x, ltB); ltB = fmaf(qB[u * 4 + 1], kk.y, ltB);
            ltB = fmaf(qB[u * 4 + 2], kk.z, ltB); ltB = fmaf(qB[u * 4 + 3], kk.w, ltB);
        }
        ltA += __shfl_xor_sync(0xffffffffu, ltA, 1);
        ltB += __shfl_xor_sync(0xffffffffu, ltB, 1);
        float wA = fmaf(eA9[l], invA, ltA + sb[58 + l]);
        float wB = fmaf(eB9[l], invB, ltB + sb[58 + l]);
#pragma unroll
        for (int d = 0; d < 16; d++) {
            float vvA = sv[(dbase + d) * 349 + sA];   // zero at masked/pad slots
            float vvB = sv[(dbase + d) * 349 + sB];
            oA[d] = fmaf(wA, vvA, oA[d]);
            oB[d] = fmaf(wB, vvB, oB[d]);
        }
    }

    if (act) {
        size_t baseA = ((size_t)b * NTOK + nA) * 256 + h * 32 + dbase;
        size_t baseB = baseA + (size_t)56 * 256;
        uint32_t* ohA = (uint32_t*)(g_ohi + baseA);
        uint32_t* olA = (uint32_t*)(g_olo + baseA);
        uint32_t* ohB = (uint32_t*)(g_ohi + baseB);
        uint32_t* olB = (uint32_t*)(g_olo + baseB);
#pragma unroll
        for (int d2 = 0; d2 < 8; d2++) {
            float a0 = oA[d2 * 2], a1 = oA[d2 * 2 + 1];
            __nv_bfloat16 ha0 = __float2bfloat16(a0);
            __nv_bfloat16 ha1 = __float2bfloat16(a1);
            __nv_bfloat162 hiA(ha0, ha1);
            __nv_bfloat162 loA(__float2bfloat16(a0 - __bfloat162float(ha0)),
                               __float2bfloat16(a1 - __bfloat162float(ha1)));
            ohA[d2] = *(uint32_t*)&hiA;
            olA[d2] = *(uint32_t*)&loA;
            float b0 = oB[d2 * 2], b1 = oB[d2 * 2 + 1];
            __nv_bfloat16 hb0 = __float2bfloat16(b0);
            __nv_bfloat16 hb1 = __float2bfloat16(b1);
            __nv_bfloat162 hiB(hb0, hb1);
            __nv_bfloat162 loB(__float2bfloat16(b0 - __bfloat162float(hb0)),
                               __float2bfloat16(b1 - __bfloat162float(hb1)));
            ohB[d2] = *(uint32_t*)&hiB;
            olB[d2] = *(uint32_t*)&loB;
        }
    }
}

// ---------------- launch -------------------------------------------------------
extern "C" void kernel_launch(void* const* d_in, const int* in_sizes, int n_in,
                              void* d_out, int out_size) {
    (void)in_sizes; (void)n_in; (void)out_size;
    const float* x     = (const float*)d_in[0];
    const float* Wq    = (const float*)d_in[1];
    const float* bq    = (const float*)d_in[2];
    const float* Wkv   = (const float*)d_in[3];
    const float* bkv   = (const float*)d_in[4];
    const float* qe    = (const float*)d_in[5];
    const float* Wsr   = (const float*)d_in[6];
    const float* bsr   = (const float*)d_in[7];
    const float* ln_g  = (const float*)d_in[8];
    const float* ln_b  = (const float*)d_in[9];
    const float* pbp   = (const float*)d_in[10];
    const float* pbl   = (const float*)d_in[11];
    const float* LT    = (const float*)d_in[12];
    const float* lb    = (const float*)d_in[13];
    const float* Wproj = (const float*)d_in[14];
    const float* bproj = (const float*)d_in[15];
    float* out = (float*)d_out;

    __nv_bfloat16 *pxhi, *pxlo, *pwthi, *pwtlo, *pwphi, *pwplo, *pohi, *polo;
    float* pbcat;
    cudaGetSymbolAddress((void**)&pxhi, g_xhi);
    cudaGetSymbolAddress((void**)&pxlo, g_xlo);
    cudaGetSymbolAddress((void**)&pwthi, g_wthi);
    cudaGetSymbolAddress((void**)&pwtlo, g_wtlo);
    cudaGetSymbolAddress((void**)&pwphi, g_wphi);
    cudaGetSymbolAddress((void**)&pwplo, g_wplo);
    cudaGetSymbolAddress((void**)&pohi, g_ohi);
    cudaGetSymbolAddress((void**)&polo, g_olo);
    cudaGetSymbolAddress((void**)&pbcat, g_bcat);

    cudaFuncSetAttribute(gemm_mma, cudaFuncAttributeMaxDynamicSharedMemorySize, 3 * STGF);
    cudaFuncSetAttribute(attn4, cudaFuncAttributeMaxDynamicSharedMemorySize,
                         ATTN_SMEM_FLOATS * 4);

    split_x<<<2048, 256>>>(x);
    pack_w<<<320, 256>>>(Wq, Wkv, Wsr, Wproj, bq, bkv, bsr, qe);

    // fused q/kv/xsr GEMM: 25088 x 1024 x 256 (bf16x3, fused stage + swizzle)
    gemm_mma<<<dim3(8, 196), 256, 3 * STGF>>>(pxhi, pxlo, pwthi, pwtlo, pbcat, nullptr, 0);

    pool_ln<<<BATCH * PLP, 256>>>(ln_g, ln_b);
    kvp_gemm<<<98, 256>>>(Wkv, bkv);

    attn4<<<dim3(14, 8, 8), 256, ATTN_SMEM_FLOATS * 4>>>(pbp, pbl, LT, lb);

    // projection GEMM: 25088 x 256 x 256 -> d_out
    gemm_mma<<<dim3(2, 196), 256, 3 * STGF>>>(pohi, polo, pwphi, pwplo, bproj, out, 1);
}

// round 14
// speedup vs baseline: 1.1079x; 1.1079x over previous
#include <cuda_runtime.h>
#include <cuda_fp16.h>
#include <math.h>
#include <stdint.h>

#define BATCH 8
#define NTOK 3136
#define MROWS (BATCH * NTOK)   // 25088
#define ASCALE 0.0625f
#define PLP 49

// ---------------- scratch ---------------------------------------------------
__device__ __align__(128) float g_q[MROWS * 256];          // (B,NH,N,HD)
__device__ __align__(128) float g_kv[MROWS * 512];         // (B,N,512)
__device__ __align__(128) float g_xsr[MROWS * 256];
__device__ __align__(128) float g_xp[BATCH * PLP * 256];
__device__ __align__(128) float g_kvp[BATCH * PLP * 512];
__device__ __align__(128) float g_bcat[1024];
__device__ __align__(128) __half g_xhi[MROWS * 256];
__device__ __align__(128) __half g_xlo[MROWS * 256];
__device__ __align__(128) __half g_wt[1024 * 256];      // W^T (N x K), fp16
__device__ __align__(128) __half g_wp[256 * 256];       // Wproj^T, fp16
__device__ __align__(128) __half g_ohi[MROWS * 256];
__device__ __align__(128) __half g_olo[MROWS * 256];

// ---------------- helpers ----------------------------------------------------
__device__ __forceinline__ uint32_t s2u(const void* p) {
    uint32_t a;
    asm("{ .reg .u64 t; cvta.to.shared.u64 t, %1; cvt.u32.u64 %0, t; }" : "=r"(a) : "l"(p));
    return a;
}
__device__ __forceinline__ void cp_async16(uint32_t saddr, const void* gaddr) {
    asm volatile("cp.async.cg.shared.global [%0], [%1], 16;" :: "r"(saddr), "l"(gaddr));
}
__device__ __forceinline__ void cp_commit() {
    asm volatile("cp.async.commit_group;");
}
__device__ __forceinline__ void ldsm4(uint32_t r[4], uint32_t addr) {
    asm volatile("ldmatrix.sync.aligned.m8n8.x4.shared.b16 {%0,%1,%2,%3}, [%4];"
                 : "=r"(r[0]), "=r"(r[1]), "=r"(r[2]), "=r"(r[3]) : "r"(addr));
}
__device__ __forceinline__ void hmma(float c[4], const uint32_t a[4],
                                     uint32_t b0, uint32_t b1) {
    asm volatile(
        "mma.sync.aligned.m16n8k16.row.col.f32.f16.f16.f32 "
        "{%0,%1,%2,%3}, {%4,%5,%6,%7}, {%8,%9}, {%0,%1,%2,%3};"
        : "+f"(c[0]), "+f"(c[1]), "+f"(c[2]), "+f"(c[3])
        : "r"(a[0]), "r"(a[1]), "r"(a[2]), "r"(a[3]), "r"(b0), "r"(b1));
}

// ---------------- prep kernels ------------------------------------------------
__global__ void split_x(const float* __restrict__ x) {
    int i = blockIdx.x * blockDim.x + threadIdx.x;
    int stride = gridDim.x * blockDim.x;
    const int TOT4 = (MROWS * 256) / 4;
    for (; i < TOT4; i += stride) {
        float4 v = ((const float4*)x)[i];
        __half h0 = __float2half_rn(v.x);
        __half h1 = __float2half_rn(v.y);
        __half h2 = __float2half_rn(v.z);
        __half h3 = __float2half_rn(v.w);
        __half2 hi0(h0, h1), hi1(h2, h3);
        __half2 lo0(__float2half_rn(v.x - __half2float(h0)),
                    __float2half_rn(v.y - __half2float(h1)));
        __half2 lo1(__float2half_rn(v.z - __half2float(h2)),
                    __float2half_rn(v.w - __half2float(h3)));
        ((uint32_t*)g_xhi)[i * 2 + 0] = *(uint32_t*)&hi0;
        ((uint32_t*)g_xhi)[i * 2 + 1] = *(uint32_t*)&hi1;
        ((uint32_t*)g_xlo)[i * 2 + 0] = *(uint32_t*)&lo0;
        ((uint32_t*)g_xlo)[i * 2 + 1] = *(uint32_t*)&lo1;
    }
}

__global__ void pack_w(const float* __restrict__ Wq, const float* __restrict__ Wkv,
                       const float* __restrict__ Wsr, const float* __restrict__ Wproj,
                       const float* __restrict__ bq, const float* __restrict__ bkv,
                       const float* __restrict__ bsr, const float* __restrict__ qe) {
    int t = blockIdx.x * blockDim.x + threadIdx.x;
    int stride = gridDim.x * blockDim.x;
    if (t < 1024)
        g_bcat[t] = (t < 256) ? (bq[t] + qe[t]) : (t < 768 ? bkv[t - 256] : bsr[t - 768]);
    const int TOT = 1024 * 256 + 256 * 256;
    for (int idx = t; idx < TOT; idx += stride) {
        float w;
        if (idx < 1024 * 256) {
            int c = idx >> 8, k = idx & 255;
            if (c < 256)      w = Wq[k * 256 + c];
            else if (c < 768) w = Wkv[k * 512 + (c - 256)];
            else              w = Wsr[k * 256 + (c - 768)];
            g_wt[idx] = __float2half_rn(w);
        } else {
            int j = idx - 1024 * 256;
            int c = j >> 8, k = j & 255;
            g_wp[j] = __float2half_rn(Wproj[k * 256 + c]);
        }
    }
}

// ---------------- HMMA fp16 2-pass GEMM: fused stage + swizzle ---------------
// Stage = Ah | Al | B tiles of 128 rows x 64B = 3 x 8192B = 24576B; 3 stages.
// Swizzle: 16B chunk c of row r stored at c ^ ((r>>1)&3).
#define STGF 24576
#define T_AL 8192
#define T_B  16384
__global__ __launch_bounds__(256, 2)
void gemm_mma(const __half* __restrict__ Ah, const __half* __restrict__ Al,
              const __half* __restrict__ B,
              const float* __restrict__ bias, float* __restrict__ Cout, int mode) {
    extern __shared__ __align__(128) uint8_t smem[];
    const int t = threadIdx.x, w = t >> 5, lane = t & 31;
    const int bm = blockIdx.y * 128, bn = blockIdx.x * 128;
    const int wm = (w >> 2) * 64, wn = (w & 3) * 32;
    const uint32_t sbase = s2u(smem);

    float c[4][4][4];
#pragma unroll
    for (int i = 0; i < 4; i++)
#pragma unroll
        for (int j = 0; j < 4; j++)
#pragma unroll
            for (int k = 0; k < 4; k++) c[i][j][k] = 0.f;

    uint32_t aRow[4], bRow[2];
#pragma unroll
    for (int mt = 0; mt < 4; mt++)
        aRow[mt] = (uint32_t)((wm + mt * 16 + (lane & 15)) * 64);
    {
        int nr = wn + (lane >> 4) * 8 + (lane & 7);
        bRow[0] = (uint32_t)(nr * 64);
        bRow[1] = (uint32_t)((nr + 16) * 64);
    }
    const uint32_t aSw = (uint32_t)(((lane & 15) >> 1) & 3);
    const uint32_t bSw = (uint32_t)(((lane & 7) >> 1) & 3);
    const uint32_t cA = (uint32_t)(lane >> 4);
    const uint32_t cB = (uint32_t)((lane >> 3) & 1);

    const int r0 = t >> 2, cc = t & 3;
    const uint32_t csw = (uint32_t)((cc ^ ((r0 >> 1) & 3)) << 4);
    const size_t aG = (size_t)(bm + r0) * 256 + cc * 8;
    const size_t bG = (size_t)(bn + r0) * 256 + cc * 8;
    const uint32_t sd0 = (uint32_t)(r0 * 64) + csw;
    const uint32_t sd1 = sd0 + 64 * 64;

#define ISSUE(IT)                                                     \
    do {                                                              \
        uint32_t _so = sbase + ((IT) % 3) * STGF;                     \
        int _ko = (IT) * 32;                                          \
        cp_async16(_so + sd0,        Ah + aG + _ko);                  \
        cp_async16(_so + sd1,        Ah + aG + 64 * 256 + _ko);       \
        cp_async16(_so + T_AL + sd0, Al + aG + _ko);                  \
        cp_async16(_so + T_AL + sd1, Al + aG + 64 * 256 + _ko);       \
        cp_async16(_so + T_B  + sd0, B  + bG + _ko);                  \
        cp_async16(_so + T_B  + sd1, B  + bG + 64 * 256 + _ko);       \
        cp_commit();                                                  \
    } while (0)

    ISSUE(0); ISSUE(1);

#pragma unroll 1
    for (int it = 0; it < 8; it++) {
        if (it < 7) asm volatile("cp.async.wait_group 1;");
        else        asm volatile("cp.async.wait_group 0;");
        __syncthreads();
        if (it + 2 < 8) ISSUE(it + 2);

        uint32_t so = sbase + (it % 3) * STGF;
#pragma unroll
        for (int ks = 0; ks < 2; ks++) {
            uint32_t swA = ((cA + 2 * ks) ^ aSw) << 4;
            uint32_t swB = ((cB + 2 * ks) ^ bSw) << 4;
            uint32_t a[4][4], b[2][4];
#pragma unroll
            for (int np = 0; np < 2; np++)
                ldsm4(b[np], so + T_B + bRow[np] + swB);
#pragma unroll
            for (int mt = 0; mt < 4; mt++) ldsm4(a[mt], so + aRow[mt] + swA);
            // Ah * B
#pragma unroll
            for (int mt = 0; mt < 4; mt++)
#pragma unroll
                for (int nt = 0; nt < 4; nt++)
                    hmma(c[mt][nt], a[mt], b[nt >> 1][(nt & 1) * 2],
                         b[nt >> 1][(nt & 1) * 2 + 1]);
            // Al * B (reload a in place, reuse b)
#pragma unroll
            for (int mt = 0; mt < 4; mt++) ldsm4(a[mt], so + T_AL + aRow[mt] + swA);
#pragma unroll
            for (int mt = 0; mt < 4; mt++)
#pragma unroll
                for (int nt = 0; nt < 4; nt++)
                    hmma(c[mt][nt], a[mt], b[nt >> 1][(nt & 1) * 2],
                         b[nt >> 1][(nt & 1) * 2 + 1]);
        }
    }
#undef ISSUE

    const int g = lane >> 2, tq = lane & 3;
#pragma unroll
    for (int mt = 0; mt < 4; mt++) {
#pragma unroll
        for (int rs = 0; rs < 2; rs++) {
            int row = bm + wm + mt * 16 + g + rs * 8;
            int b = row / NTOK, n = row - b * NTOK;
#pragma unroll
            for (int nt = 0; nt < 4; nt++) {
#pragma unroll
                for (int cs = 0; cs < 2; cs++) {
                    int col = bn + wn + nt * 8 + tq * 2 + cs;
                    float v = c[mt][nt][rs * 2 + cs] + bias[col];
                    if (mode == 0) {
                        if (col < 256) {
                            int h = col >> 5, d = col & 31;
                            g_q[(((size_t)b * 8 + h) * NTOK + n) * 32 + d] = v;
                        } else if (col < 768) {
                            g_kv[((size_t)b * NTOK + n) * 512 + (col - 256)] = v;
                        } else {
                            float gl = 0.5f * v * (1.f + erff(v * 0.70710678118654752f));
                            g_xsr[((size_t)b * NTOK + n) * 256 + (col - 768)] = gl;
                        }
                    } else {
                        Cout[(size_t)row * 256 + col] = v;
                    }
                }
            }
        }
    }
}

// ---------------- pool (8x8 mean) + layernorm, warp-shuffle reductions --------
__global__ void pool_ln(const float* __restrict__ ln_g, const float* __restrict__ ln_b) {
    int bp = blockIdx.x;
    int b = bp / PLP, p = bp % PLP;
    int ph = p / 7, pw = p % 7;
    int c = threadIdx.x;
    int wid = c >> 5, lane = c & 31;
    float s = 0.f;
    const float* base = g_xsr + (size_t)b * NTOK * 256 + c;
#pragma unroll
    for (int ii = 0; ii < 8; ii++)
#pragma unroll
        for (int jj = 0; jj < 8; jj++)
            s += base[(size_t)((ph * 8 + ii) * 56 + pw * 8 + jj) * 256];
    s *= (1.f / 64.f);

    __shared__ float wred[8];
    __shared__ float stat[2];
    float v = s;
#pragma unroll
    for (int o = 16; o; o >>= 1) v += __shfl_xor_sync(0xffffffffu, v, o);
    if (lane == 0) wred[wid] = v;
    __syncthreads();
    if (c == 0) {
        float tot = 0.f;
#pragma unroll
        for (int u = 0; u < 8; u++) tot += wred[u];
        stat[0] = tot * (1.f / 256.f);
    }
    __syncthreads();
    float mu = stat[0];
    float d = s - mu;
    v = d * d;
#pragma unroll
    for (int o = 16; o; o >>= 1) v += __shfl_xor_sync(0xffffffffu, v, o);
    if (lane == 0) wred[wid] = v;
    __syncthreads();
    if (c == 0) {
        float tot = 0.f;
#pragma unroll
        for (int u = 0; u < 8; u++) tot += wred[u];
        stat[1] = tot * (1.f / 256.f);
    }
    __syncthreads();
    float var = stat[1];
    g_xp[(size_t)bp * 256 + c] = d * rsqrtf(var + 1e-5f) * ln_g[c] + ln_b[c];
}

// ---------------- small kvp GEMM (392 x 512 x 256), 4 rows/block -------------
__global__ __launch_bounds__(256)
void kvp_gemm(const float* __restrict__ Wkv, const float* __restrict__ bkv) {
    __shared__ float sx[4][256];
    int t = threadIdx.x;
    int r0 = blockIdx.x * 4;
#pragma unroll
    for (int r = 0; r < 4; r++) sx[r][t] = g_xp[(size_t)(r0 + r) * 256 + t];
    __syncthreads();
    int c0 = t * 2;
    float a0[4], a1[4];
#pragma unroll
    for (int r = 0; r < 4; r++) { a0[r] = 0.f; a1[r] = 0.f; }
#pragma unroll 4
    for (int k = 0; k < 256; k++) {
        float2 w = *(const float2*)(Wkv + (size_t)k * 512 + c0);
#pragma unroll
        for (int r = 0; r < 4; r++) {
            float xv = sx[r][k];
            a0[r] = fmaf(xv, w.x, a0[r]);
            a1[r] = fmaf(xv, w.y, a1[r]);
        }
    }
    float b0 = bkv[c0], b1 = bkv[c0 + 1];
#pragma unroll
    for (int r = 0; r < 4; r++) {
        g_kvp[(size_t)(r0 + r) * 512 + c0]     = a0[r] + b0;
        g_kvp[(size_t)(r0 + r) * 512 + c0 + 1] = a1[r] + b1;
    }
}

// ---------------- attention v4: 2 tokens/thread, d-split, streaming -----------
#define SK_OFF   0
#define SV_OFF   11168
#define SKP_OFF  22336
#define SVP_OFF  23904
#define SLT_OFF  25472
#define SB_OFF   25760
#define ATTN_SMEM_FLOATS 25828

__global__ __launch_bounds__(256, 2)
void attn4(const float* __restrict__ pbp, const float* __restrict__ pbl,
           const float* __restrict__ LT, const float* __restrict__ lb) {
    extern __shared__ __align__(16) float sm[];
    float* sk  = sm + SK_OFF;
    float* sv  = sm + SV_OFF;
    float* skp = sm + SKP_OFF;
    float* svp = sm + SVP_OFF;
    float* sLT = sm + SLT_OFF;
    float* sb  = sm + SB_OFF;

    const int t = threadIdx.x, w = t >> 5, lane = t & 31;
    const int h  = blockIdx.y;
    const int b  = blockIdx.z;
    const int i0 = blockIdx.x * 4;

    // zero ONLY the value staging
    {
        float4* z = (float4*)sv;
        for (int idx = t; idx < 11168 / 4; idx += 256)
            z[idx] = make_float4(0.f, 0.f, 0.f, 0.f);
    }
    if (t < 49)       sb[t] = pbp[h * 49 + t];
    else if (t < 58)  sb[t] = pbl[h * 9 + (t - 49)];
    else if (t < 67)  sb[t] = lb[h * 9 + (t - 58)];
    __syncthreads();

    for (int tok = t; tok < 336; tok += 256) {
        int ri = tok / 56, cc = tok - ri * 56;
        int gr = i0 - 1 + ri;
        if ((unsigned)gr < 56u) {
            int n = gr * 56 + cc;
            const float4* kg = (const float4*)(g_kv + ((size_t)(b * NTOK + n) * 512 + h * 32));
            int sbs = ri * 58 + cc + 1;
#pragma unroll
            for (int u = 0; u < 8; u++) {
                float4 kk = kg[u];
                float4 vv = kg[64 + u];
                sk[(u * 4 + 0) * 349 + sbs] = kk.x;
                sk[(u * 4 + 1) * 349 + sbs] = kk.y;
                sk[(u * 4 + 2) * 349 + sbs] = kk.z;
                sk[(u * 4 + 3) * 349 + sbs] = kk.w;
                sv[(u * 4 + 0) * 349 + sbs] = vv.x;
                sv[(u * 4 + 1) * 349 + sbs] = vv.y;
                sv[(u * 4 + 2) * 349 + sbs] = vv.z;
                sv[(u * 4 + 3) * 349 + sbs] = vv.w;
            }
        }
    }
    for (int idx = t; idx < 49 * 8; idx += 256) {
        int p = idx >> 3, d4 = idx & 7;
        const float4* src = (const float4*)(g_kvp + ((size_t)(b * PLP + p) * 512 + h * 32));
        *(float4*)(skp + p * 32 + d4 * 4) = src[d4];
        *(float4*)(svp + p * 32 + d4 * 4) = src[64 + d4];
    }
    for (int idx = t; idx < 288; idx += 256) {
        int d = idx / 9, l = idx - d * 9;
        sLT[l * 32 + d] = LT[(h * 32 + d) * 9 + l];
    }
    __syncthreads();

    const int rp2 = w >> 2;
    const int jt  = w & 3;
    const int jj  = lane >> 1;
    const int dh  = lane & 1;
    const bool act = jj < 14;
    const int j  = jt * 14 + (act ? jj : 0);
    const int iA = i0 + rp2 * 2;
    const int nA = iA * 56 + j;
    const int dbase = dh * 16;

    float qA[16], qB[16];
    {
        const float4* qsA = (const float4*)(g_q + ((((size_t)b * 8 + h) * NTOK + nA) * 32 + dbase));
        const float4* qsB = (const float4*)(g_q + ((((size_t)b * 8 + h) * NTOK + nA + 56) * 32 + dbase));
#pragma unroll
        for (int u = 0; u < 4; u++) {
            float4 a = qsA[u], c = qsB[u];
            qA[u * 4 + 0] = a.x; qA[u * 4 + 1] = a.y; qA[u * 4 + 2] = a.z; qA[u * 4 + 3] = a.w;
            qB[u * 4 + 0] = c.x; qB[u * 4 + 1] = c.y; qB[u * 4 + 2] = c.z; qB[u * 4 + 3] = c.w;
        }
    }

    float eA9[9], eB9[9];
    float SA = 0.f, SB = 0.f;

#pragma unroll
    for (int l = 0; l < 9; l++) {
        int di = l / 3, dj = l - di * 3;
        int sA = (rp2 * 2 + di) * 58 + j + dj;
        int sB = sA + 58;
        float dA = 0.f, dB = 0.f;
#pragma unroll
        for (int d = 0; d < 16; d++) {
            dA = fmaf(qA[d], sk[(dbase + d) * 349 + sA], dA);
            dB = fmaf(qB[d], sk[(dbase + d) * 349 + sB], dB);
        }
        dA += __shfl_xor_sync(0xffffffffu, dA, 1);
        dB += __shfl_xor_sync(0xffffffffu, dB, 1);
        bool vA = act && ((unsigned)(iA + di - 1) < 56u) && ((unsigned)(j + dj - 1) < 56u);
        bool vB = act && ((unsigned)(iA + di) < 56u) && ((unsigned)(j + dj - 1) < 56u);
        float eA = vA ? __expf(dA * ASCALE + sb[49 + l]) : 0.f;
        float eB = vB ? __expf(dB * ASCALE + sb[49 + l]) : 0.f;
        eA9[l] = eA; eB9[l] = eB;
        SA += eA; SB += eB;
    }

    float oA[16], oB[16];
#pragma unroll
    for (int d = 0; d < 16; d++) { oA[d] = 0.f; oB[d] = 0.f; }
#pragma unroll 7
    for (int p = 0; p < 49; p++) {
        const float4* kp4 = (const float4*)(skp + p * 32 + dbase);
        float dA = 0.f, dB = 0.f;
#pragma unroll
        for (int u = 0; u < 4; u++) {
            float4 kk = kp4[u];
            dA = fmaf(qA[u * 4 + 0], kk.x, dA); dA = fmaf(qA[u * 4 + 1], kk.y, dA);
            dA = fmaf(qA[u * 4 + 2], kk.z, dA); dA = fmaf(qA[u * 4 + 3], kk.w, dA);
            dB = fmaf(qB[u * 4 + 0], kk.x, dB); dB = fmaf(qB[u * 4 + 1], kk.y, dB);
            dB = fmaf(qB[u * 4 + 2], kk.z, dB); dB = fmaf(qB[u * 4 + 3], kk.w, dB);
        }
        dA += __shfl_xor_sync(0xffffffffu, dA, 1);
        dB += __shfl_xor_sync(0xffffffffu, dB, 1);
        float eA = __expf(dA * ASCALE + sb[p]);
        float eB = __expf(dB * ASCALE + sb[p]);
        SA += eA; SB += eB;
        const float4* vp4 = (const float4*)(svp + p * 32 + dbase);
#pragma unroll
        for (int u = 0; u < 4; u++) {
            float4 vv = vp4[u];
            oA[u * 4 + 0] = fmaf(eA, vv.x, oA[u * 4 + 0]);
            oA[u * 4 + 1] = fmaf(eA, vv.y, oA[u * 4 + 1]);
            oA[u * 4 + 2] = fmaf(eA, vv.z, oA[u * 4 + 2]);
            oA[u * 4 + 3] = fmaf(eA, vv.w, oA[u * 4 + 3]);
            oB[u * 4 + 0] = fmaf(eB, vv.x, oB[u * 4 + 0]);
            oB[u * 4 + 1] = fmaf(eB, vv.y, oB[u * 4 + 1]);
            oB[u * 4 + 2] = fmaf(eB, vv.z, oB[u * 4 + 2]);
            oB[u * 4 + 3] = fmaf(eB, vv.w, oB[u * 4 + 3]);
        }
    }

    float invA = 1.f / SA, invB = 1.f / SB;
#pragma unroll
    for (int d = 0; d < 16; d++) { oA[d] *= invA; oB[d] *= invB; }

#pragma unroll
    for (int l = 0; l < 9; l++) {
        int di = l / 3, dj = l - di * 3;
        int sA = (rp2 * 2 + di) * 58 + j + dj;
        int sB = sA + 58;
        const float4* lt4 = (const float4*)(sLT + l * 32 + dbase);
        float ltA = 0.f, ltB = 0.f;
#pragma unroll
        for (int u = 0; u < 4; u++) {
            float4 kk = lt4[u];
            ltA = fmaf(qA[u * 4 + 0], kk.x, ltA); ltA = fmaf(qA[u * 4 + 1], kk.y, ltA);
            ltA = fmaf(qA[u * 4 + 2], kk.z, ltA); ltA = fmaf(qA[u * 4 + 3], kk.w, ltA);
            ltB = fmaf(qB[u * 4 + 0], kk.x, ltB); ltB = fmaf(qB[u * 4 + 1], kk.y, ltB);
            ltB = fmaf(qB[u * 4 + 2], kk.z, ltB); ltB = fmaf(qB[u * 4 + 3], kk.w, ltB);
        }
        ltA += __shfl_xor_sync(0xffffffffu, ltA, 1);
        ltB += __shfl_xor_sync(0xffffffffu, ltB, 1);
        float wA = fmaf(eA9[l], invA, ltA + sb[58 + l]);
        float wB = fmaf(eB9[l], invB, ltB + sb[58 + l]);
#pragma unroll
        for (int d = 0; d < 16; d++) {
            float vvA = sv[(dbase + d) * 349 + sA];
            float vvB = sv[(dbase + d) * 349 + sB];
            oA[d] = fmaf(wA, vvA, oA[d]);
            oB[d] = fmaf(wB, vvB, oB[d]);
        }
    }

    if (act) {
        size_t baseA = ((size_t)b * NTOK + nA) * 256 + h * 32 + dbase;
        size_t baseB = baseA + (size_t)56 * 256;
        uint32_t* ohA = (uint32_t*)(g_ohi + baseA);
        uint32_t* olA = (uint32_t*)(g_olo + baseA);
        uint32_t* ohB = (uint32_t*)(g_ohi + baseB);
        uint32_t* olB = (uint32_t*)(g_olo + baseB);
#pragma unroll
        for (int d2 = 0; d2 < 8; d2++) {
            float a0 = oA[d2 * 2], a1 = oA[d2 * 2 + 1];
            __half ha0 = __float2half_rn(a0);
            __half ha1 = __float2half_rn(a1);
            __half2 hiA(ha0, ha1);
            __half2 loA(__float2half_rn(a0 - __half2float(ha0)),
                        __float2half_rn(a1 - __half2float(ha1)));
            ohA[d2] = *(uint32_t*)&hiA;
            olA[d2] = *(uint32_t*)&loA;
            float b0 = oB[d2 * 2], b1 = oB[d2 * 2 + 1];
            __half hb0 = __float2half_rn(b0);
            __half hb1 = __float2half_rn(b1);
            __half2 hiB(hb0, hb1);
            __half2 loB(__float2half_rn(b0 - __half2float(hb0)),
                        __float2half_rn(b1 - __half2float(hb1)));
            ohB[d2] = *(uint32_t*)&hiB;
            olB[d2] = *(uint32_t*)&loB;
        }
    }
}

// ---------------- launch -------------------------------------------------------
extern "C" void kernel_launch(void* const* d_in, const int* in_sizes, int n_in,
                              void* d_out, int out_size) {
    (void)in_sizes; (void)n_in; (void)out_size;
    const float* x     = (const float*)d_in[0];
    const float* Wq    = (const float*)d_in[1];
    const float* bq    = (const float*)d_in[2];
    const float* Wkv   = (const float*)d_in[3];
    const float* bkv   = (const float*)d_in[4];
    const float* qe    = (const float*)d_in[5];
    const float* Wsr   = (const float*)d_in[6];
    const float* bsr   = (const float*)d_in[7];
    const float* ln_g  = (const float*)d_in[8];
    const float* ln_b  = (const float*)d_in[9];
    const float* pbp   = (const float*)d_in[10];
    const float* pbl   = (const float*)d_in[11];
    const float* LT    = (const float*)d_in[12];
    const float* lb    = (const float*)d_in[13];
    const float* Wproj = (const float*)d_in[14];
    const float* bproj = (const float*)d_in[15];
    float* out = (float*)d_out;

    __half *pxhi, *pxlo, *pwt, *pwp, *pohi, *polo;
    float* pbcat;
    cudaGetSymbolAddress((void**)&pxhi, g_xhi);
    cudaGetSymbolAddress((void**)&pxlo, g_xlo);
    cudaGetSymbolAddress((void**)&pwt, g_wt);
    cudaGetSymbolAddress((void**)&pwp, g_wp);
    cudaGetSymbolAddress((void**)&pohi, g_ohi);
    cudaGetSymbolAddress((void**)&polo, g_olo);
    cudaGetSymbolAddress((void**)&pbcat, g_bcat);

    cudaFuncSetAttribute(gemm_mma, cudaFuncAttributeMaxDynamicSharedMemorySize, 3 * STGF);
    cudaFuncSetAttribute(attn4, cudaFuncAttributeMaxDynamicSharedMemorySize,
                         ATTN_SMEM_FLOATS * 4);

    split_x<<<2048, 256>>>(x);
    pack_w<<<320, 256>>>(Wq, Wkv, Wsr, Wproj, bq, bkv, bsr, qe);

    // fused q/kv/xsr GEMM: 25088 x 1024 x 256 (fp16 2-pass on HMMA)
    gemm_mma<<<dim3(8, 196), 256, 3 * STGF>>>(pxhi, pxlo, pwt, pbcat, nullptr, 0);

    pool_ln<<<BATCH * PLP, 256>>>(ln_g, ln_b);
    kvp_gemm<<<98, 256>>>(Wkv, bkv);

    attn4<<<dim3(14, 8, 8), 256, ATTN_SMEM_FLOATS * 4>>>(pbp, pbl, LT, lb);

    // projection GEMM: 25088 x 256 x 256 -> d_out
    gemm_mma<<<dim3(2, 196), 256, 3 * STGF>>>(pohi, polo, pwp, bproj, out, 1);
}

// round 15
// speedup vs baseline: 1.2528x; 1.1308x over previous
#include <cuda_runtime.h>
#include <cuda_fp16.h>
#include <math.h>
#include <stdint.h>

#define BATCH 8
#define NTOK 3136
#define MROWS (BATCH * NTOK)   // 25088
#define ASCALE 0.0625f
#define PLP 49

// ---------------- scratch ---------------------------------------------------
__device__ __align__(128) float g_q[MROWS * 256];          // (B,NH,N,HD)
__device__ __align__(128) float g_kv[MROWS * 512];         // (B,N,512)
__device__ __align__(128) float g_xsr[MROWS * 256];
__device__ __align__(128) float g_xp[BATCH * PLP * 256];
__device__ __align__(128) float g_kvp[BATCH * PLP * 512];
__device__ __align__(128) float g_bcat[1024];
__device__ __align__(128) __half g_xh[MROWS * 256];
__device__ __align__(128) __half g_wt[1024 * 256];      // W^T (N x K), fp16
__device__ __align__(128) __half g_wp[256 * 256];       // Wproj^T, fp16
__device__ __align__(128) __half g_oh[MROWS * 256];

// ---------------- helpers ----------------------------------------------------
__device__ __forceinline__ uint32_t s2u(const void* p) {
    uint32_t a;
    asm("{ .reg .u64 t; cvta.to.shared.u64 t, %1; cvt.u32.u64 %0, t; }" : "=r"(a) : "l"(p));
    return a;
}
__device__ __forceinline__ void cp_async16(uint32_t saddr, const void* gaddr) {
    asm volatile("cp.async.cg.shared.global [%0], [%1], 16;" :: "r"(saddr), "l"(gaddr));
}
__device__ __forceinline__ void cp_commit() {
    asm volatile("cp.async.commit_group;");
}
__device__ __forceinline__ void ldsm4(uint32_t r[4], uint32_t addr) {
    asm volatile("ldmatrix.sync.aligned.m8n8.x4.shared.b16 {%0,%1,%2,%3}, [%4];"
                 : "=r"(r[0]), "=r"(r[1]), "=r"(r[2]), "=r"(r[3]) : "r"(addr));
}
__device__ __forceinline__ void hmma(float c[4], const uint32_t a[4],
                                     uint32_t b0, uint32_t b1) {
    asm volatile(
        "mma.sync.aligned.m16n8k16.row.col.f32.f16.f16.f32 "
        "{%0,%1,%2,%3}, {%4,%5,%6,%7}, {%8,%9}, {%0,%1,%2,%3};"
        : "+f"(c[0]), "+f"(c[1]), "+f"(c[2]), "+f"(c[3])
        : "r"(a[0]), "r"(a[1]), "r"(a[2]), "r"(a[3]), "r"(b0), "r"(b1));
}

// ---------------- prep kernels ------------------------------------------------
__global__ void conv_x(const float* __restrict__ x) {
    int i = blockIdx.x * blockDim.x + threadIdx.x;
    int stride = gridDim.x * blockDim.x;
    const int TOT4 = (MROWS * 256) / 4;
    for (; i < TOT4; i += stride) {
        float4 v = ((const float4*)x)[i];
        __half2 h0(__float2half_rn(v.x), __float2half_rn(v.y));
        __half2 h1(__float2half_rn(v.z), __float2half_rn(v.w));
        ((uint32_t*)g_xh)[i * 2 + 0] = *(uint32_t*)&h0;
        ((uint32_t*)g_xh)[i * 2 + 1] = *(uint32_t*)&h1;
    }
}

__global__ void pack_w(const float* __restrict__ Wq, const float* __restrict__ Wkv,
                       const float* __restrict__ Wsr, const float* __restrict__ Wproj,
                       const float* __restrict__ bq, const float* __restrict__ bkv,
                       const float* __restrict__ bsr, const float* __restrict__ qe) {
    int t = blockIdx.x * blockDim.x + threadIdx.x;
    int stride = gridDim.x * blockDim.x;
    if (t < 1024)
        g_bcat[t] = (t < 256) ? (bq[t] + qe[t]) : (t < 768 ? bkv[t - 256] : bsr[t - 768]);
    const int TOT = 1024 * 256 + 256 * 256;
    for (int idx = t; idx < TOT; idx += stride) {
        float w;
        if (idx < 1024 * 256) {
            int c = idx >> 8, k = idx & 255;
            if (c < 256)      w = Wq[k * 256 + c];
            else if (c < 768) w = Wkv[k * 512 + (c - 256)];
            else              w = Wsr[k * 256 + (c - 768)];
            g_wt[idx] = __float2half_rn(w);
        } else {
            int j = idx - 1024 * 256;
            int c = j >> 8, k = j & 255;
            g_wp[j] = __float2half_rn(Wproj[k * 256 + c]);
        }
    }
}

// ---------------- HMMA fp16 single-pass GEMM: swizzled, 4-stage K=32 ---------
// Stage = A | B tiles of 128 rows x 64B = 2 x 8192B = 16384B; 4 stages = 64KB.
// Swizzle: 16B chunk c of row r stored at c ^ ((r>>1)&3).
#define STGF 16384
#define T_B  8192
__global__ __launch_bounds__(256, 2)
void gemm_mma(const __half* __restrict__ A, const __half* __restrict__ B,
              const float* __restrict__ bias, float* __restrict__ Cout, int mode) {
    extern __shared__ __align__(128) uint8_t smem[];
    const int t = threadIdx.x, w = t >> 5, lane = t & 31;
    const int bm = blockIdx.y * 128, bn = blockIdx.x * 128;
    const int wm = (w >> 2) * 64, wn = (w & 3) * 32;
    const uint32_t sbase = s2u(smem);

    float c[4][4][4];
#pragma unroll
    for (int i = 0; i < 4; i++)
#pragma unroll
        for (int j = 0; j < 4; j++)
#pragma unroll
            for (int k = 0; k < 4; k++) c[i][j][k] = 0.f;

    uint32_t aRow[4], bRow[2];
#pragma unroll
    for (int mt = 0; mt < 4; mt++)
        aRow[mt] = (uint32_t)((wm + mt * 16 + (lane & 15)) * 64);
    {
        int nr = wn + (lane >> 4) * 8 + (lane & 7);
        bRow[0] = (uint32_t)(T_B + nr * 64);
        bRow[1] = (uint32_t)(T_B + (nr + 16) * 64);
    }
    const uint32_t aSw = (uint32_t)(((lane & 15) >> 1) & 3);
    const uint32_t bSw = (uint32_t)(((lane & 7) >> 1) & 3);
    const uint32_t cA = (uint32_t)(lane >> 4);
    const uint32_t cB = (uint32_t)((lane >> 3) & 1);

    const int r0 = t >> 2, cc = t & 3;
    const uint32_t csw = (uint32_t)((cc ^ ((r0 >> 1) & 3)) << 4);
    const size_t aG = (size_t)(bm + r0) * 256 + cc * 8;
    const size_t bG = (size_t)(bn + r0) * 256 + cc * 8;
    const uint32_t sd0 = (uint32_t)(r0 * 64) + csw;
    const uint32_t sd1 = sd0 + 64 * 64;

#define ISSUE(IT)                                                     \
    do {                                                              \
        uint32_t _so = sbase + ((IT) & 3) * STGF;                     \
        int _ko = (IT) * 32;                                          \
        cp_async16(_so + sd0,       A + aG + _ko);                    \
        cp_async16(_so + sd1,       A + aG + 64 * 256 + _ko);         \
        cp_async16(_so + T_B + sd0, B + bG + _ko);                    \
        cp_async16(_so + T_B + sd1, B + bG + 64 * 256 + _ko);         \
        cp_commit();                                                  \
    } while (0)

    ISSUE(0); ISSUE(1); ISSUE(2);

#pragma unroll 1
    for (int it = 0; it < 8; it++) {
        if (it < 6)       asm volatile("cp.async.wait_group 2;");
        else if (it == 6) asm volatile("cp.async.wait_group 1;");
        else              asm volatile("cp.async.wait_group 0;");
        __syncthreads();
        if (it + 3 < 8) ISSUE(it + 3);

        uint32_t so = sbase + (it & 3) * STGF;
#pragma unroll
        for (int ks = 0; ks < 2; ks++) {
            uint32_t swA = ((cA + 2 * ks) ^ aSw) << 4;
            uint32_t swB = ((cB + 2 * ks) ^ bSw) << 4;
            uint32_t a[4][4], b[2][4];
#pragma unroll
            for (int np = 0; np < 2; np++)
                ldsm4(b[np], so + bRow[np] + swB);
#pragma unroll
            for (int mt = 0; mt < 4; mt++) ldsm4(a[mt], so + aRow[mt] + swA);
#pragma unroll
            for (int mt = 0; mt < 4; mt++)
#pragma unroll
                for (int nt = 0; nt < 4; nt++)
                    hmma(c[mt][nt], a[mt], b[nt >> 1][(nt & 1) * 2],
                         b[nt >> 1][(nt & 1) * 2 + 1]);
        }
    }
#undef ISSUE

    const int g = lane >> 2, tq = lane & 3;
#pragma unroll
    for (int mt = 0; mt < 4; mt++) {
#pragma unroll
        for (int rs = 0; rs < 2; rs++) {
            int row = bm + wm + mt * 16 + g + rs * 8;
            int b = row / NTOK, n = row - b * NTOK;
#pragma unroll
            for (int nt = 0; nt < 4; nt++) {
#pragma unroll
                for (int cs = 0; cs < 2; cs++) {
                    int col = bn + wn + nt * 8 + tq * 2 + cs;
                    float v = c[mt][nt][rs * 2 + cs] + bias[col];
                    if (mode == 0) {
                        if (col < 256) {
                            int h = col >> 5, d = col & 31;
                            g_q[(((size_t)b * 8 + h) * NTOK + n) * 32 + d] = v;
                        } else if (col < 768) {
                            g_kv[((size_t)b * NTOK + n) * 512 + (col - 256)] = v;
                        } else {
                            float gl = 0.5f * v * (1.f + erff(v * 0.70710678118654752f));
                            g_xsr[((size_t)b * NTOK + n) * 256 + (col - 768)] = gl;
                        }
                    } else {
                        Cout[(size_t)row * 256 + col] = v;
                    }
                }
            }
        }
    }
}

// ---------------- pool (8x8 mean) + layernorm --------------------------------
__global__ void pool_ln(const float* __restrict__ ln_g, const float* __restrict__ ln_b) {
    int bp = blockIdx.x;
    int b = bp / PLP, p = bp % PLP;
    int ph = p / 7, pw = p % 7;
    int c = threadIdx.x;
    int wid = c >> 5, lane = c & 31;
    float s = 0.f;
    const float* base = g_xsr + (size_t)b * NTOK * 256 + c;
#pragma unroll
    for (int ii = 0; ii < 8; ii++)
#pragma unroll
        for (int jj = 0; jj < 8; jj++)
            s += base[(size_t)((ph * 8 + ii) * 56 + pw * 8 + jj) * 256];
    s *= (1.f / 64.f);

    __shared__ float wred[8];
    __shared__ float stat[2];
    float v = s;
#pragma unroll
    for (int o = 16; o; o >>= 1) v += __shfl_xor_sync(0xffffffffu, v, o);
    if (lane == 0) wred[wid] = v;
    __syncthreads();
    if (c == 0) {
        float tot = 0.f;
#pragma unroll
        for (int u = 0; u < 8; u++) tot += wred[u];
        stat[0] = tot * (1.f / 256.f);
    }
    __syncthreads();
    float mu = stat[0];
    float d = s - mu;
    v = d * d;
#pragma unroll
    for (int o = 16; o; o >>= 1) v += __shfl_xor_sync(0xffffffffu, v, o);
    if (lane == 0) wred[wid] = v;
    __syncthreads();
    if (c == 0) {
        float tot = 0.f;
#pragma unroll
        for (int u = 0; u < 8; u++) tot += wred[u];
        stat[1] = tot * (1.f / 256.f);
    }
    __syncthreads();
    float var = stat[1];
    g_xp[(size_t)bp * 256 + c] = d * rsqrtf(var + 1e-5f) * ln_g[c] + ln_b[c];
}

// ---------------- small kvp GEMM (392 x 512 x 256), 4 rows/block -------------
__global__ __launch_bounds__(256)
void kvp_gemm(const float* __restrict__ Wkv, const float* __restrict__ bkv) {
    __shared__ float sx[4][256];
    int t = threadIdx.x;
    int r0 = blockIdx.x * 4;
#pragma unroll
    for (int r = 0; r < 4; r++) sx[r][t] = g_xp[(size_t)(r0 + r) * 256 + t];
    __syncthreads();
    int c0 = t * 2;
    float a0[4], a1[4];
#pragma unroll
    for (int r = 0; r < 4; r++) { a0[r] = 0.f; a1[r] = 0.f; }
#pragma unroll 4
    for (int k = 0; k < 256; k++) {
        float2 w = *(const float2*)(Wkv + (size_t)k * 512 + c0);
#pragma unroll
        for (int r = 0; r < 4; r++) {
            float xv = sx[r][k];
            a0[r] = fmaf(xv, w.x, a0[r]);
            a1[r] = fmaf(xv, w.y, a1[r]);
        }
    }
    float b0 = bkv[c0], b1 = bkv[c0 + 1];
#pragma unroll
    for (int r = 0; r < 4; r++) {
        g_kvp[(size_t)(r0 + r) * 512 + c0]     = a0[r] + b0;
        g_kvp[(size_t)(r0 + r) * 512 + c0 + 1] = a1[r] + b1;
    }
}

// ---------------- attention v4: 2 tokens/thread, d-split, streaming -----------
#define SK_OFF   0
#define SV_OFF   11168
#define SKP_OFF  22336
#define SVP_OFF  23904
#define SLT_OFF  25472
#define SB_OFF   25760
#define ATTN_SMEM_FLOATS 25828

__global__ __launch_bounds__(256, 2)
void attn4(const float* __restrict__ pbp, const float* __restrict__ pbl,
           const float* __restrict__ LT, const float* __restrict__ lb) {
    extern __shared__ __align__(16) float sm[];
    float* sk  = sm + SK_OFF;
    float* sv  = sm + SV_OFF;
    float* skp = sm + SKP_OFF;
    float* svp = sm + SVP_OFF;
    float* sLT = sm + SLT_OFF;
    float* sb  = sm + SB_OFF;

    const int t = threadIdx.x, w = t >> 5, lane = t & 31;
    const int h  = blockIdx.y;
    const int b  = blockIdx.z;
    const int i0 = blockIdx.x * 4;

    {
        float4* z = (float4*)sv;
        for (int idx = t; idx < 11168 / 4; idx += 256)
            z[idx] = make_float4(0.f, 0.f, 0.f, 0.f);
    }
    if (t < 49)       sb[t] = pbp[h * 49 + t];
    else if (t < 58)  sb[t] = pbl[h * 9 + (t - 49)];
    else if (t < 67)  sb[t] = lb[h * 9 + (t - 58)];
    __syncthreads();

    for (int tok = t; tok < 336; tok += 256) {
        int ri = tok / 56, cc = tok - ri * 56;
        int gr = i0 - 1 + ri;
        if ((unsigned)gr < 56u) {
            int n = gr * 56 + cc;
            const float4* kg = (const float4*)(g_kv + ((size_t)(b * NTOK + n) * 512 + h * 32));
            int sbs = ri * 58 + cc + 1;
#pragma unroll
            for (int u = 0; u < 8; u++) {
                float4 kk = kg[u];
                float4 vv = kg[64 + u];
                sk[(u * 4 + 0) * 349 + sbs] = kk.x;
                sk[(u * 4 + 1) * 349 + sbs] = kk.y;
                sk[(u * 4 + 2) * 349 + sbs] = kk.z;
                sk[(u * 4 + 3) * 349 + sbs] = kk.w;
                sv[(u * 4 + 0) * 349 + sbs] = vv.x;
                sv[(u * 4 + 1) * 349 + sbs] = vv.y;
                sv[(u * 4 + 2) * 349 + sbs] = vv.z;
                sv[(u * 4 + 3) * 349 + sbs] = vv.w;
            }
        }
    }
    for (int idx = t; idx < 49 * 8; idx += 256) {
        int p = idx >> 3, d4 = idx & 7;
        const float4* src = (const float4*)(g_kvp + ((size_t)(b * PLP + p) * 512 + h * 32));
        *(float4*)(skp + p * 32 + d4 * 4) = src[d4];
        *(float4*)(svp + p * 32 + d4 * 4) = src[64 + d4];
    }
    for (int idx = t; idx < 288; idx += 256) {
        int d = idx / 9, l = idx - d * 9;
        sLT[l * 32 + d] = LT[(h * 32 + d) * 9 + l];
    }
    __syncthreads();

    const int rp2 = w >> 2;
    const int jt  = w & 3;
    const int jj  = lane >> 1;
    const int dh  = lane & 1;
    const bool act = jj < 14;
    const int j  = jt * 14 + (act ? jj : 0);
    const int iA = i0 + rp2 * 2;
    const int nA = iA * 56 + j;
    const int dbase = dh * 16;

    float qA[16], qB[16];
    {
        const float4* qsA = (const float4*)(g_q + ((((size_t)b * 8 + h) * NTOK + nA) * 32 + dbase));
        const float4* qsB = (const float4*)(g_q + ((((size_t)b * 8 + h) * NTOK + nA + 56) * 32 + dbase));
#pragma unroll
        for (int u = 0; u < 4; u++) {
            float4 a = qsA[u], c = qsB[u];
            qA[u * 4 + 0] = a.x; qA[u * 4 + 1] = a.y; qA[u * 4 + 2] = a.z; qA[u * 4 + 3] = a.w;
            qB[u * 4 + 0] = c.x; qB[u * 4 + 1] = c.y; qB[u * 4 + 2] = c.z; qB[u * 4 + 3] = c.w;
        }
    }

    float eA9[9], eB9[9];
    float SA = 0.f, SB = 0.f;

#pragma unroll
    for (int l = 0; l < 9; l++) {
        int di = l / 3, dj = l - di * 3;
        int sA = (rp2 * 2 + di) * 58 + j + dj;
        int sB = sA + 58;
        float dA = 0.f, dB = 0.f;
#pragma unroll
        for (int d = 0; d < 16; d++) {
            dA = fmaf(qA[d], sk[(dbase + d) * 349 + sA], dA);
            dB = fmaf(qB[d], sk[(dbase + d) * 349 + sB], dB);
        }
        dA += __shfl_xor_sync(0xffffffffu, dA, 1);
        dB += __shfl_xor_sync(0xffffffffu, dB, 1);
        bool vA = act && ((unsigned)(iA + di - 1) < 56u) && ((unsigned)(j + dj - 1) < 56u);
        bool vB = act && ((unsigned)(iA + di) < 56u) && ((unsigned)(j + dj - 1) < 56u);
        float eA = vA ? __expf(dA * ASCALE + sb[49 + l]) : 0.f;
        float eB = vB ? __expf(dB * ASCALE + sb[49 + l]) : 0.f;
        eA9[l] = eA; eB9[l] = eB;
        SA += eA; SB += eB;
    }

    float oA[16], oB[16];
#pragma unroll
    for (int d = 0; d < 16; d++) { oA[d] = 0.f; oB[d] = 0.f; }
#pragma unroll 7
    for (int p = 0; p < 49; p++) {
        const float4* kp4 = (const float4*)(skp + p * 32 + dbase);
        float dA = 0.f, dB = 0.f;
#pragma unroll
        for (int u = 0; u < 4; u++) {
            float4 kk = kp4[u];
            dA = fmaf(qA[u * 4 + 0], kk.x, dA); dA = fmaf(qA[u * 4 + 1], kk.y, dA);
            dA = fmaf(qA[u * 4 + 2], kk.z, dA); dA = fmaf(qA[u * 4 + 3], kk.w, dA);
            dB = fmaf(qB[u * 4 + 0], kk.x, dB); dB = fmaf(qB[u * 4 + 1], kk.y, dB);
            dB = fmaf(qB[u * 4 + 2], kk.z, dB); dB = fmaf(qB[u * 4 + 3], kk.w, dB);
        }
        dA += __shfl_xor_sync(0xffffffffu, dA, 1);
        dB += __shfl_xor_sync(0xffffffffu, dB, 1);
        float eA = __expf(dA * ASCALE + sb[p]);
        float eB = __expf(dB * ASCALE + sb[p]);
        SA += eA; SB += eB;
        const float4* vp4 = (const float4*)(svp + p * 32 + dbase);
#pragma unroll
        for (int u = 0; u < 4; u++) {
            float4 vv = vp4[u];
            oA[u * 4 + 0] = fmaf(eA, vv.x, oA[u * 4 + 0]);
            oA[u * 4 + 1] = fmaf(eA, vv.y, oA[u * 4 + 1]);
            oA[u * 4 + 2] = fmaf(eA, vv.z, oA[u * 4 + 2]);
            oA[u * 4 + 3] = fmaf(eA, vv.w, oA[u * 4 + 3]);
            oB[u * 4 + 0] = fmaf(eB, vv.x, oB[u * 4 + 0]);
            oB[u * 4 + 1] = fmaf(eB, vv.y, oB[u * 4 + 1]);
            oB[u * 4 + 2] = fmaf(eB, vv.z, oB[u * 4 + 2]);
            oB[u * 4 + 3] = fmaf(eB, vv.w, oB[u * 4 + 3]);
        }
    }

    float invA = 1.f / SA, invB = 1.f / SB;
#pragma unroll
    for (int d = 0; d < 16; d++) { oA[d] *= invA; oB[d] *= invB; }

#pragma unroll
    for (int l = 0; l < 9; l++) {
        int di = l / 3, dj = l - di * 3;
        int sA = (rp2 * 2 + di) * 58 + j + dj;
        int sB = sA + 58;
        const float4* lt4 = (const float4*)(sLT + l * 32 + dbase);
        float ltA = 0.f, ltB = 0.f;
#pragma unroll
        for (int u = 0; u < 4; u++) {
            float4 kk = lt4[u];
            ltA = fmaf(qA[u * 4 + 0], kk.x, ltA); ltA = fmaf(qA[u * 4 + 1], kk.y, ltA);
            ltA = fmaf(qA[u * 4 + 2], kk.z, ltA); ltA = fmaf(qA[u * 4 + 3], kk.w, ltA);
            ltB = fmaf(qB[u * 4 + 0], kk.x, ltB); ltB = fmaf(qB[u * 4 + 1], kk.y, ltB);
            ltB = fmaf(qB[u * 4 + 2], kk.z, ltB); ltB = fmaf(qB[u * 4 + 3], kk.w, ltB);
        }
        ltA += __shfl_xor_sync(0xffffffffu, ltA, 1);
        ltB += __shfl_xor_sync(0xffffffffu, ltB, 1);
        float wA = fmaf(eA9[l], invA, ltA + sb[58 + l]);
        float wB = fmaf(eB9[l], invB, ltB + sb[58 + l]);
#pragma unroll
        for (int d = 0; d < 16; d++) {
            float vvA = sv[(dbase + d) * 349 + sA];
            float vvB = sv[(dbase + d) * 349 + sB];
            oA[d] = fmaf(wA, vvA, oA[d]);
            oB[d] = fmaf(wB, vvB, oB[d]);
        }
    }

    if (act) {
        size_t baseA = ((size_t)b * NTOK + nA) * 256 + h * 32 + dbase;
        size_t baseB = baseA + (size_t)56 * 256;
        uint32_t* ohA = (uint32_t*)(g_oh + baseA);
        uint32_t* ohB = (uint32_t*)(g_oh + baseB);
#pragma unroll
        for (int d2 = 0; d2 < 8; d2++) {
            __half2 hA(__float2half_rn(oA[d2 * 2]), __float2half_rn(oA[d2 * 2 + 1]));
            __half2 hB(__float2half_rn(oB[d2 * 2]), __float2half_rn(oB[d2 * 2 + 1]));
            ohA[d2] = *(uint32_t*)&hA;
            ohB[d2] = *(uint32_t*)&hB;
        }
    }
}

// ---------------- launch -------------------------------------------------------
extern "C" void kernel_launch(void* const* d_in, const int* in_sizes, int n_in,
                              void* d_out, int out_size) {
    (void)in_sizes; (void)n_in; (void)out_size;
    const float* x     = (const float*)d_in[0];
    const float* Wq    = (const float*)d_in[1];
    const float* bq    = (const float*)d_in[2];
    const float* Wkv   = (const float*)d_in[3];
    const float* bkv   = (const float*)d_in[4];
    const float* qe    = (const float*)d_in[5];
    const float* Wsr   = (const float*)d_in[6];
    const float* bsr   = (const float*)d_in[7];
    const float* ln_g  = (const float*)d_in[8];
    const float* ln_b  = (const float*)d_in[9];
    const float* pbp   = (const float*)d_in[10];
    const float* pbl   = (const float*)d_in[11];
    const float* LT    = (const float*)d_in[12];
    const float* lb    = (const float*)d_in[13];
    const float* Wproj = (const float*)d_in[14];
    const float* bproj = (const float*)d_in[15];
    float* out = (float*)d_out;

    __half *pxh, *pwt, *pwp, *poh;
    float* pbcat;
    cudaGetSymbolAddress((void**)&pxh, g_xh);
    cudaGetSymbolAddress((void**)&pwt, g_wt);
    cudaGetSymbolAddress((void**)&pwp, g_wp);
    cudaGetSymbolAddress((void**)&poh, g_oh);
    cudaGetSymbolAddress((void**)&pbcat, g_bcat);

    cudaFuncSetAttribute(gemm_mma, cudaFuncAttributeMaxDynamicSharedMemorySize, 4 * STGF);
    cudaFuncSetAttribute(attn4, cudaFuncAttributeMaxDynamicSharedMemorySize,
                         ATTN_SMEM_FLOATS * 4);

    conv_x<<<2048, 256>>>(x);
    pack_w<<<320, 256>>>(Wq, Wkv, Wsr, Wproj, bq, bkv, bsr, qe);

    // fused q/kv/xsr GEMM: 25088 x 1024 x 256 (fp16 single pass)
    gemm_mma<<<dim3(8, 196), 256, 4 * STGF>>>(pxh, pwt, pbcat, nullptr, 0);

    pool_ln<<<BATCH * PLP, 256>>>(ln_g, ln_b);
    kvp_gemm<<<98, 256>>>(Wkv, bkv);

    attn4<<<dim3(14, 8, 8), 256, ATTN_SMEM_FLOATS * 4>>>(pbp, pbl, LT, lb);

    // projection GEMM: 25088 x 256 x 256 -> d_out (fp16 single pass)
    gemm_mma<<<dim3(2, 196), 256, 4 * STGF>>>(poh, pwp, bproj, out, 1);
}

// round 16
// speedup vs baseline: 1.4322x; 1.1432x over previous
#include <cuda_runtime.h>
#include <cuda_fp16.h>
#include <math.h>
#include <stdint.h>

#define BATCH 8
#define NTOK 3136
#define MROWS (BATCH * NTOK)   // 25088
#define ASCALE 0.0625f
#define PLP 49

// ---------------- scratch ---------------------------------------------------
__device__ __align__(128) float g_q[MROWS * 256];          // (B,NH,N,HD) fp32
__device__ __align__(128) __half g_kvh[MROWS * 512];       // kv in fp16
__device__ __align__(128) float g_xsr[MROWS * 256];
__device__ __align__(128) float g_xp[BATCH * PLP * 256];
__device__ __align__(128) __half g_kvph[BATCH * PLP * 512];
__device__ __align__(128) float g_bcat[1024];
__device__ __align__(128) __half g_xh[MROWS * 256];
__device__ __align__(128) __half g_wt[1024 * 256];      // W^T (N x K), fp16
__device__ __align__(128) __half g_wp[256 * 256];       // Wproj^T, fp16
__device__ __align__(128) __half g_oh[MROWS * 256];

// ---------------- helpers ----------------------------------------------------
__device__ __forceinline__ uint32_t s2u(const void* p) {
    uint32_t a;
    asm("{ .reg .u64 t; cvta.to.shared.u64 t, %1; cvt.u32.u64 %0, t; }" : "=r"(a) : "l"(p));
    return a;
}
__device__ __forceinline__ void cp_async16(uint32_t saddr, const void* gaddr) {
    asm volatile("cp.async.cg.shared.global [%0], [%1], 16;" :: "r"(saddr), "l"(gaddr));
}
__device__ __forceinline__ void cp_commit() {
    asm volatile("cp.async.commit_group;");
}
__device__ __forceinline__ void ldsm4(uint32_t r[4], uint32_t addr) {
    asm volatile("ldmatrix.sync.aligned.m8n8.x4.shared.b16 {%0,%1,%2,%3}, [%4];"
                 : "=r"(r[0]), "=r"(r[1]), "=r"(r[2]), "=r"(r[3]) : "r"(addr));
}
__device__ __forceinline__ void hmma(float c[4], const uint32_t a[4],
                                     uint32_t b0, uint32_t b1) {
    asm volatile(
        "mma.sync.aligned.m16n8k16.row.col.f32.f16.f16.f32 "
        "{%0,%1,%2,%3}, {%4,%5,%6,%7}, {%8,%9}, {%0,%1,%2,%3};"
        : "+f"(c[0]), "+f"(c[1]), "+f"(c[2]), "+f"(c[3])
        : "r"(a[0]), "r"(a[1]), "r"(a[2]), "r"(a[3]), "r"(b0), "r"(b1));
}

// ---------------- prep kernels ------------------------------------------------
__global__ void conv_x(const float* __restrict__ x) {
    int i = blockIdx.x * blockDim.x + threadIdx.x;
    int stride = gridDim.x * blockDim.x;
    const int TOT4 = (MROWS * 256) / 4;
    for (; i < TOT4; i += stride) {
        float4 v = ((const float4*)x)[i];
        __half2 h0(__float2half_rn(v.x), __float2half_rn(v.y));
        __half2 h1(__float2half_rn(v.z), __float2half_rn(v.w));
        ((uint32_t*)g_xh)[i * 2 + 0] = *(uint32_t*)&h0;
        ((uint32_t*)g_xh)[i * 2 + 1] = *(uint32_t*)&h1;
    }
}

__global__ void pack_w(const float* __restrict__ Wq, const float* __restrict__ Wkv,
                       const float* __restrict__ Wsr, const float* __restrict__ Wproj,
                       const float* __restrict__ bq, const float* __restrict__ bkv,
                       const float* __restrict__ bsr, const float* __restrict__ qe) {
    int t = blockIdx.x * blockDim.x + threadIdx.x;
    int stride = gridDim.x * blockDim.x;
    if (t < 1024)
        g_bcat[t] = (t < 256) ? (bq[t] + qe[t]) : (t < 768 ? bkv[t - 256] : bsr[t - 768]);
    const int TOT = 1024 * 256 + 256 * 256;
    for (int idx = t; idx < TOT; idx += stride) {
        float w;
        if (idx < 1024 * 256) {
            int c = idx >> 8, k = idx & 255;
            if (c < 256)      w = Wq[k * 256 + c];
            else if (c < 768) w = Wkv[k * 512 + (c - 256)];
            else              w = Wsr[k * 256 + (c - 768)];
            g_wt[idx] = __float2half_rn(w);
        } else {
            int j = idx - 1024 * 256;
            int c = j >> 8, k = j & 255;
            g_wp[j] = __float2half_rn(Wproj[k * 256 + c]);
        }
    }
}

// ---------------- HMMA fp16 single-pass GEMM: swizzled, 4-stage K=32 ---------
#define STGF 16384
#define T_B  8192
__global__ __launch_bounds__(256, 2)
void gemm_mma(const __half* __restrict__ A, const __half* __restrict__ B,
              const float* __restrict__ bias, float* __restrict__ Cout, int mode) {
    extern __shared__ __align__(128) uint8_t smem[];
    const int t = threadIdx.x, w = t >> 5, lane = t & 31;
    const int bm = blockIdx.y * 128, bn = blockIdx.x * 128;
    const int wm = (w >> 2) * 64, wn = (w & 3) * 32;
    const uint32_t sbase = s2u(smem);

    float c[4][4][4];
#pragma unroll
    for (int i = 0; i < 4; i++)
#pragma unroll
        for (int j = 0; j < 4; j++)
#pragma unroll
            for (int k = 0; k < 4; k++) c[i][j][k] = 0.f;

    uint32_t aRow[4], bRow[2];
#pragma unroll
    for (int mt = 0; mt < 4; mt++)
        aRow[mt] = (uint32_t)((wm + mt * 16 + (lane & 15)) * 64);
    {
        int nr = wn + (lane >> 4) * 8 + (lane & 7);
        bRow[0] = (uint32_t)(T_B + nr * 64);
        bRow[1] = (uint32_t)(T_B + (nr + 16) * 64);
    }
    const uint32_t aSw = (uint32_t)(((lane & 15) >> 1) & 3);
    const uint32_t bSw = (uint32_t)(((lane & 7) >> 1) & 3);
    const uint32_t cA = (uint32_t)(lane >> 4);
    const uint32_t cB = (uint32_t)((lane >> 3) & 1);

    const int r0 = t >> 2, cc = t & 3;
    const uint32_t csw = (uint32_t)((cc ^ ((r0 >> 1) & 3)) << 4);
    const size_t aG = (size_t)(bm + r0) * 256 + cc * 8;
    const size_t bG = (size_t)(bn + r0) * 256 + cc * 8;
    const uint32_t sd0 = (uint32_t)(r0 * 64) + csw;
    const uint32_t sd1 = sd0 + 64 * 64;

#define ISSUE(IT)                                                     \
    do {                                                              \
        uint32_t _so = sbase + ((IT) & 3) * STGF;                     \
        int _ko = (IT) * 32;                                          \
        cp_async16(_so + sd0,       A + aG + _ko);                    \
        cp_async16(_so + sd1,       A + aG + 64 * 256 + _ko);         \
        cp_async16(_so + T_B + sd0, B + bG + _ko);                    \
        cp_async16(_so + T_B + sd1, B + bG + 64 * 256 + _ko);         \
        cp_commit();                                                  \
    } while (0)

    ISSUE(0); ISSUE(1); ISSUE(2);

#pragma unroll 1
    for (int it = 0; it < 8; it++) {
        if (it < 6)       asm volatile("cp.async.wait_group 2;");
        else if (it == 6) asm volatile("cp.async.wait_group 1;");
        else              asm volatile("cp.async.wait_group 0;");
        __syncthreads();
        if (it + 3 < 8) ISSUE(it + 3);

        uint32_t so = sbase + (it & 3) * STGF;
#pragma unroll
        for (int ks = 0; ks < 2; ks++) {
            uint32_t swA = ((cA + 2 * ks) ^ aSw) << 4;
            uint32_t swB = ((cB + 2 * ks) ^ bSw) << 4;
            uint32_t a[4][4], b[2][4];
#pragma unroll
            for (int np = 0; np < 2; np++)
                ldsm4(b[np], so + bRow[np] + swB);
#pragma unroll
            for (int mt = 0; mt < 4; mt++) ldsm4(a[mt], so + aRow[mt] + swA);
#pragma unroll
            for (int mt = 0; mt < 4; mt++)
#pragma unroll
                for (int nt = 0; nt < 4; nt++)
                    hmma(c[mt][nt], a[mt], b[nt >> 1][(nt & 1) * 2],
                         b[nt >> 1][(nt & 1) * 2 + 1]);
        }
    }
#undef ISSUE

    const int g = lane >> 2, tq = lane & 3;
#pragma unroll
    for (int mt = 0; mt < 4; mt++) {
#pragma unroll
        for (int rs = 0; rs < 2; rs++) {
            int row = bm + wm + mt * 16 + g + rs * 8;
            int b = row / NTOK, n = row - b * NTOK;
#pragma unroll
            for (int nt = 0; nt < 4; nt++) {
                int col0 = bn + wn + nt * 8 + tq * 2;
                float v0 = c[mt][nt][rs * 2 + 0] + bias[col0];
                float v1 = c[mt][nt][rs * 2 + 1] + bias[col0 + 1];
                if (mode == 0) {
                    if (col0 < 256) {
                        int h = col0 >> 5, d = col0 & 31;
                        float* qdst = g_q + (((size_t)b * 8 + h) * NTOK + n) * 32 + d;
                        qdst[0] = v0; qdst[1] = v1;
                    } else if (col0 < 768) {
                        __half2 hv(__float2half_rn(v0), __float2half_rn(v1));
                        *(uint32_t*)(g_kvh + ((size_t)b * NTOK + n) * 512 + (col0 - 256)) =
                            *(uint32_t*)&hv;
                    } else {
                        float g0 = 0.5f * v0 * (1.f + erff(v0 * 0.70710678118654752f));
                        float g1 = 0.5f * v1 * (1.f + erff(v1 * 0.70710678118654752f));
                        float* xdst = g_xsr + ((size_t)b * NTOK + n) * 256 + (col0 - 768);
                        xdst[0] = g0; xdst[1] = g1;
                    }
                } else {
                    Cout[(size_t)row * 256 + col0] = v0;
                    Cout[(size_t)row * 256 + col0 + 1] = v1;
                }
            }
        }
    }
}

// ---------------- pool (8x8 mean) + layernorm --------------------------------
__global__ void pool_ln(const float* __restrict__ ln_g, const float* __restrict__ ln_b) {
    int bp = blockIdx.x;
    int b = bp / PLP, p = bp % PLP;
    int ph = p / 7, pw = p % 7;
    int c = threadIdx.x;
    int wid = c >> 5, lane = c & 31;
    float s = 0.f;
    const float* base = g_xsr + (size_t)b * NTOK * 256 + c;
#pragma unroll
    for (int ii = 0; ii < 8; ii++)
#pragma unroll
        for (int jj = 0; jj < 8; jj++)
            s += base[(size_t)((ph * 8 + ii) * 56 + pw * 8 + jj) * 256];
    s *= (1.f / 64.f);

    __shared__ float wred[8];
    __shared__ float stat[2];
    float v = s;
#pragma unroll
    for (int o = 16; o; o >>= 1) v += __shfl_xor_sync(0xffffffffu, v, o);
    if (lane == 0) wred[wid] = v;
    __syncthreads();
    if (c == 0) {
        float tot = 0.f;
#pragma unroll
        for (int u = 0; u < 8; u++) tot += wred[u];
        stat[0] = tot * (1.f / 256.f);
    }
    __syncthreads();
    float mu = stat[0];
    float d = s - mu;
    v = d * d;
#pragma unroll
    for (int o = 16; o; o >>= 1) v += __shfl_xor_sync(0xffffffffu, v, o);
    if (lane == 0) wred[wid] = v;
    __syncthreads();
    if (c == 0) {
        float tot = 0.f;
#pragma unroll
        for (int u = 0; u < 8; u++) tot += wred[u];
        stat[1] = tot * (1.f / 256.f);
    }
    __syncthreads();
    float var = stat[1];
    g_xp[(size_t)bp * 256 + c] = d * rsqrtf(var + 1e-5f) * ln_g[c] + ln_b[c];
}

// ---------------- small kvp GEMM (392 x 512 x 256), half2 output -------------
__global__ __launch_bounds__(256)
void kvp_gemm(const float* __restrict__ Wkv, const float* __restrict__ bkv) {
    __shared__ float sx[4][256];
    int t = threadIdx.x;
    int r0 = blockIdx.x * 4;
#pragma unroll
    for (int r = 0; r < 4; r++) sx[r][t] = g_xp[(size_t)(r0 + r) * 256 + t];
    __syncthreads();
    int c0 = t * 2;
    float a0[4], a1[4];
#pragma unroll
    for (int r = 0; r < 4; r++) { a0[r] = 0.f; a1[r] = 0.f; }
#pragma unroll 4
    for (int k = 0; k < 256; k++) {
        float2 w = *(const float2*)(Wkv + (size_t)k * 512 + c0);
#pragma unroll
        for (int r = 0; r < 4; r++) {
            float xv = sx[r][k];
            a0[r] = fmaf(xv, w.x, a0[r]);
            a1[r] = fmaf(xv, w.y, a1[r]);
        }
    }
    float b0 = bkv[c0], b1 = bkv[c0 + 1];
#pragma unroll
    for (int r = 0; r < 4; r++) {
        __half2 hv(__float2half_rn(a0[r] + b0), __float2half_rn(a1[r] + b1));
        *(uint32_t*)(g_kvph + (size_t)(r0 + r) * 512 + c0) = *(uint32_t*)&hv;
    }
}

// ---------------- attention v5: fp16 K/V in smem (packed half2) ---------------
// layout (bytes): sk2 half2[16*349] @0, sv2 @22336, skp2 half2[49*16] @44672,
//                 svp2 @47808, sLT float[288] @50944, sb float[68] @52096
#define SK_OFF   0
#define SV_OFF   22336
#define SKP_OFF  44672
#define SVP_OFF  47808
#define SLT_OFF  50944
#define SB_OFF   52096
#define ATTN_SMEM_BYTES 52384

__global__ __launch_bounds__(256, 2)
void attn5(const float* __restrict__ pbp, const float* __restrict__ pbl,
           const float* __restrict__ LT, const float* __restrict__ lb) {
    extern __shared__ __align__(128) uint8_t smraw[];
    __half2* sk  = (__half2*)(smraw + SK_OFF);
    __half2* sv  = (__half2*)(smraw + SV_OFF);
    __half2* skp = (__half2*)(smraw + SKP_OFF);
    __half2* svp = (__half2*)(smraw + SVP_OFF);
    float*   sLT = (float*)(smraw + SLT_OFF);
    float*   sb  = (float*)(smraw + SB_OFF);

    const int t = threadIdx.x, w = t >> 5, lane = t & 31;
    const int h  = blockIdx.y;
    const int b  = blockIdx.z;
    const int i0 = blockIdx.x * 4;

    // zero ONLY the value staging (22336 B = 1396 float4)
    {
        float4* z = (float4*)sv;
        for (int idx = t; idx < 1396; idx += 256)
            z[idx] = make_float4(0.f, 0.f, 0.f, 0.f);
    }
    if (t < 49)       sb[t] = pbp[h * 49 + t];
    else if (t < 58)  sb[t] = pbl[h * 9 + (t - 49)];
    else if (t < 67)  sb[t] = lb[h * 9 + (t - 58)];
    __syncthreads();

    // stage local k/v rows i0-1 .. i0+4 (6 rows); dp-major (dp = d/2), stride 349
    for (int tok = t; tok < 336; tok += 256) {
        int ri = tok / 56, cc = tok - ri * 56;
        int gr = i0 - 1 + ri;
        if ((unsigned)gr < 56u) {
            int n = gr * 56 + cc;
            const uint4* kg = (const uint4*)(g_kvh + ((size_t)(b * NTOK + n) * 512 + h * 32));
            int sbs = ri * 58 + cc + 1;
#pragma unroll
            for (int u = 0; u < 4; u++) {
                uint4 kk = kg[u];       // halves d = 8u .. 8u+7
                uint4 vv = kg[32 + u];  // V at +256 halves
                const uint32_t* kw = (const uint32_t*)&kk;
                const uint32_t* vw = (const uint32_t*)&vv;
#pragma unroll
                for (int q2 = 0; q2 < 4; q2++) {
                    ((uint32_t*)sk)[(4 * u + q2) * 349 + sbs] = kw[q2];
                    ((uint32_t*)sv)[(4 * u + q2) * 349 + sbs] = vw[q2];
                }
            }
        }
    }
    // stage pooled k/v (49 keys x 4 uint4 each)
    for (int idx = t; idx < 49 * 4; idx += 256) {
        int p = idx >> 2, u = idx & 3;
        const uint4* src = (const uint4*)(g_kvph + ((size_t)(b * PLP + p) * 512 + h * 32));
        ((uint4*)(skp + p * 16))[u] = src[u];
        ((uint4*)(svp + p * 16))[u] = src[32 + u];
    }
    for (int idx = t; idx < 288; idx += 256) {
        int d = idx / 9, l = idx - d * 9;
        sLT[l * 32 + d] = LT[(h * 32 + d) * 9 + l];
    }
    __syncthreads();

    const int rp2 = w >> 2;
    const int jt  = w & 3;
    const int jj  = lane >> 1;
    const int dh  = lane & 1;
    const bool act = jj < 14;
    const int j  = jt * 14 + (act ? jj : 0);
    const int iA = i0 + rp2 * 2;
    const int nA = iA * 56 + j;
    const int dbase = dh * 16;   // d range; dp range = dh*8 .. dh*8+7
    const int dpb = dh * 8;

    float qA[16], qB[16];
    {
        const float4* qsA = (const float4*)(g_q + ((((size_t)b * 8 + h) * NTOK + nA) * 32 + dbase));
        const float4* qsB = (const float4*)(g_q + ((((size_t)b * 8 + h) * NTOK + nA + 56) * 32 + dbase));
#pragma unroll
        for (int u = 0; u < 4; u++) {
            float4 a = qsA[u], c = qsB[u];
            qA[u * 4 + 0] = a.x; qA[u * 4 + 1] = a.y; qA[u * 4 + 2] = a.z; qA[u * 4 + 3] = a.w;
            qB[u * 4 + 0] = c.x; qB[u * 4 + 1] = c.y; qB[u * 4 + 2] = c.z; qB[u * 4 + 3] = c.w;
        }
    }

    float eA9[9], eB9[9];
    float SA = 0.f, SB = 0.f;

    // phase 1: local logits
#pragma unroll
    for (int l = 0; l < 9; l++) {
        int di = l / 3, dj = l - di * 3;
        int sA = (rp2 * 2 + di) * 58 + j + dj;
        int sB = sA + 58;
        float dA = 0.f, dB = 0.f;
#pragma unroll
        for (int dp = 0; dp < 8; dp++) {
            float2 fA = __half22float2(sk[(dpb + dp) * 349 + sA]);
            float2 fB = __half22float2(sk[(dpb + dp) * 349 + sB]);
            dA = fmaf(qA[2 * dp], fA.x, dA); dA = fmaf(qA[2 * dp + 1], fA.y, dA);
            dB = fmaf(qB[2 * dp], fB.x, dB); dB = fmaf(qB[2 * dp + 1], fB.y, dB);
        }
        dA += __shfl_xor_sync(0xffffffffu, dA, 1);
        dB += __shfl_xor_sync(0xffffffffu, dB, 1);
        bool vA = act && ((unsigned)(iA + di - 1) < 56u) && ((unsigned)(j + dj - 1) < 56u);
        bool vB = act && ((unsigned)(iA + di) < 56u) && ((unsigned)(j + dj - 1) < 56u);
        float eA = vA ? __expf(dA * ASCALE + sb[49 + l]) : 0.f;
        float eB = vB ? __expf(dB * ASCALE + sb[49 + l]) : 0.f;
        eA9[l] = eA; eB9[l] = eB;
        SA += eA; SB += eB;
    }

    // phase 2: pooled streaming
    float oA[16], oB[16];
#pragma unroll
    for (int d = 0; d < 16; d++) { oA[d] = 0.f; oB[d] = 0.f; }
#pragma unroll 7
    for (int p = 0; p < 49; p++) {
        const uint4* kp = (const uint4*)(skp + p * 16 + dpb);
        uint4 k0 = kp[0], k1 = kp[1];
        const __half2* kh0 = (const __half2*)&k0;
        const __half2* kh1 = (const __half2*)&k1;
        float dA = 0.f, dB = 0.f;
#pragma unroll
        for (int u = 0; u < 4; u++) {
            float2 f0 = __half22float2(kh0[u]);
            float2 f1 = __half22float2(kh1[u]);
            dA = fmaf(qA[2 * u], f0.x, dA); dA = fmaf(qA[2 * u + 1], f0.y, dA);
            dA = fmaf(qA[8 + 2 * u], f1.x, dA); dA = fmaf(qA[9 + 2 * u], f1.y, dA);
            dB = fmaf(qB[2 * u], f0.x, dB); dB = fmaf(qB[2 * u + 1], f0.y, dB);
            dB = fmaf(qB[8 + 2 * u], f1.x, dB); dB = fmaf(qB[9 + 2 * u], f1.y, dB);
        }
        dA += __shfl_xor_sync(0xffffffffu, dA, 1);
        dB += __shfl_xor_sync(0xffffffffu, dB, 1);
        float eA = __expf(dA * ASCALE + sb[p]);
        float eB = __expf(dB * ASCALE + sb[p]);
        SA += eA; SB += eB;
        const uint4* vp = (const uint4*)(svp + p * 16 + dpb);
        uint4 v0 = vp[0], v1 = vp[1];
        const __half2* vh0 = (const __half2*)&v0;
        const __half2* vh1 = (const __half2*)&v1;
#pragma unroll
        for (int u = 0; u < 4; u++) {
            float2 f0 = __half22float2(vh0[u]);
            float2 f1 = __half22float2(vh1[u]);
            oA[2 * u]     = fmaf(eA, f0.x, oA[2 * u]);
            oA[2 * u + 1] = fmaf(eA, f0.y, oA[2 * u + 1]);
            oA[8 + 2 * u] = fmaf(eA, f1.x, oA[8 + 2 * u]);
            oA[9 + 2 * u] = fmaf(eA, f1.y, oA[9 + 2 * u]);
            oB[2 * u]     = fmaf(eB, f0.x, oB[2 * u]);
            oB[2 * u + 1] = fmaf(eB, f0.y, oB[2 * u + 1]);
            oB[8 + 2 * u] = fmaf(eB, f1.x, oB[8 + 2 * u]);
            oB[9 + 2 * u] = fmaf(eB, f1.y, oB[9 + 2 * u]);
        }
    }

    // phase 3
    float invA = 1.f / SA, invB = 1.f / SB;
#pragma unroll
    for (int d = 0; d < 16; d++) { oA[d] *= invA; oB[d] *= invB; }

    // phase 4: local values + LT
#pragma unroll
    for (int l = 0; l < 9; l++) {
        int di = l / 3, dj = l - di * 3;
        int sA = (rp2 * 2 + di) * 58 + j + dj;
        int sB = sA + 58;
        const float4* lt4 = (const float4*)(sLT + l * 32 + dbase);
        float ltA = 0.f, ltB = 0.f;
#pragma unroll
        for (int u = 0; u < 4; u++) {
            float4 kk = lt4[u];
            ltA = fmaf(qA[u * 4 + 0], kk.x, ltA); ltA = fmaf(qA[u * 4 + 1], kk.y, ltA);
            ltA = fmaf(qA[u * 4 + 2], kk.z, ltA); ltA = fmaf(qA[u * 4 + 3], kk.w, ltA);
            ltB = fmaf(qB[u * 4 + 0], kk.x, ltB); ltB = fmaf(qB[u * 4 + 1], kk.y, ltB);
            ltB = fmaf(qB[u * 4 + 2], kk.z, ltB); ltB = fmaf(qB[u * 4 + 3], kk.w, ltB);
        }
        ltA += __shfl_xor_sync(0xffffffffu, ltA, 1);
        ltB += __shfl_xor_sync(0xffffffffu, ltB, 1);
        float wA = fmaf(eA9[l], invA, ltA + sb[58 + l]);
        float wB = fmaf(eB9[l], invB, ltB + sb[58 + l]);
#pragma unroll
        for (int dp = 0; dp < 8; dp++) {
            float2 fA = __half22float2(sv[(dpb + dp) * 349 + sA]);
            float2 fB = __half22float2(sv[(dpb + dp) * 349 + sB]);
            oA[2 * dp]     = fmaf(wA, fA.x, oA[2 * dp]);
            oA[2 * dp + 1] = fmaf(wA, fA.y, oA[2 * dp + 1]);
            oB[2 * dp]     = fmaf(wB, fB.x, oB[2 * dp]);
            oB[2 * dp + 1] = fmaf(wB, fB.y, oB[2 * dp + 1]);
        }
    }

    if (act) {
        size_t baseA = ((size_t)b * NTOK + nA) * 256 + h * 32 + dbase;
        size_t baseB = baseA + (size_t)56 * 256;
        uint32_t* ohA = (uint32_t*)(g_oh + baseA);
        uint32_t* ohB = (uint32_t*)(g_oh + baseB);
#pragma unroll
        for (int d2 = 0; d2 < 8; d2++) {
            __half2 hA(__float2half_rn(oA[d2 * 2]), __float2half_rn(oA[d2 * 2 + 1]));
            __half2 hB(__float2half_rn(oB[d2 * 2]), __float2half_rn(oB[d2 * 2 + 1]));
            ohA[d2] = *(uint32_t*)&hA;
            ohB[d2] = *(uint32_t*)&hB;
        }
    }
}

// ---------------- launch -------------------------------------------------------
extern "C" void kernel_launch(void* const* d_in, const int* in_sizes, int n_in,
                              void* d_out, int out_size) {
    (void)in_sizes; (void)n_in; (void)out_size;
    const float* x     = (const float*)d_in[0];
    const float* Wq    = (const float*)d_in[1];
    const float* bq    = (const float*)d_in[2];
    const float* Wkv   = (const float*)d_in[3];
    const float* bkv   = (const float*)d_in[4];
    const float* qe    = (const float*)d_in[5];
    const float* Wsr   = (const float*)d_in[6];
    const float* bsr   = (const float*)d_in[7];
    const float* ln_g  = (const float*)d_in[8];
    const float* ln_b  = (const float*)d_in[9];
    const float* pbp   = (const float*)d_in[10];
    const float* pbl   = (const float*)d_in[11];
    const float* LT    = (const float*)d_in[12];
    const float* lb    = (const float*)d_in[13];
    const float* Wproj = (const float*)d_in[14];
    const float* bproj = (const float*)d_in[15];
    float* out = (float*)d_out;

    __half *pxh, *pwt, *pwp, *poh;
    float* pbcat;
    cudaGetSymbolAddress((void**)&pxh, g_xh);
    cudaGetSymbolAddress((void**)&pwt, g_wt);
    cudaGetSymbolAddress((void**)&pwp, g_wp);
    cudaGetSymbolAddress((void**)&poh, g_oh);
    cudaGetSymbolAddress((void**)&pbcat, g_bcat);

    cudaFuncSetAttribute(gemm_mma, cudaFuncAttributeMaxDynamicSharedMemorySize, 4 * STGF);
    cudaFuncSetAttribute(attn5, cudaFuncAttributeMaxDynamicSharedMemorySize,
                         ATTN_SMEM_BYTES);

    conv_x<<<2048, 256>>>(x);
    pack_w<<<320, 256>>>(Wq, Wkv, Wsr, Wproj, bq, bkv, bsr, qe);

    // fused q/kv/xsr GEMM: 25088 x 1024 x 256 (fp16 single pass)
    gemm_mma<<<dim3(8, 196), 256, 4 * STGF>>>(pxh, pwt, pbcat, nullptr, 0);

    pool_ln<<<BATCH * PLP, 256>>>(ln_g, ln_b);
    kvp_gemm<<<98, 256>>>(Wkv, bkv);

    attn5<<<dim3(14, 8, 8), 256, ATTN_SMEM_BYTES>>>(pbp, pbl, LT, lb);

    // projection GEMM: 25088 x 256 x 256 -> d_out (fp16 single pass)
    gemm_mma<<<dim3(2, 196), 256, 4 * STGF>>>(poh, pwp, bproj, out, 1);
}

// round 17
// speedup vs baseline: 1.4815x; 1.0344x over previous
#include <cuda_runtime.h>
#include <cuda_fp16.h>
#include <math.h>
#include <stdint.h>

#define BATCH 8
#define NTOK 3136
#define MROWS (BATCH * NTOK)   // 25088
#define ASCALE 0.0625f
#define PLP 49

// ---------------- scratch ---------------------------------------------------
__device__ __align__(128) __half g_qh[MROWS * 256];        // (B,NH,N,HD) fp16
__device__ __align__(128) __half g_kvh[MROWS * 512];       // kv fp16
__device__ __align__(128) __half g_xsrh[MROWS * 256];      // gelu(x@Wsr) fp16
__device__ __align__(128) float g_xp[BATCH * PLP * 256];
__device__ __align__(128) __half g_kvph[BATCH * PLP * 512];
__device__ __align__(128) float g_bcat[1024];
__device__ __align__(128) __half g_xh[MROWS * 256];
__device__ __align__(128) __half g_wt[1024 * 256];      // W^T (N x K), fp16
__device__ __align__(128) __half g_wp[256 * 256];       // Wproj^T, fp16
__device__ __align__(128) __half g_oh[MROWS * 256];

// ---------------- helpers ----------------------------------------------------
__device__ __forceinline__ uint32_t s2u(const void* p) {
    uint32_t a;
    asm("{ .reg .u64 t; cvta.to.shared.u64 t, %1; cvt.u32.u64 %0, t; }" : "=r"(a) : "l"(p));
    return a;
}
__device__ __forceinline__ void cp_async16(uint32_t saddr, const void* gaddr) {
    asm volatile("cp.async.cg.shared.global [%0], [%1], 16;" :: "r"(saddr), "l"(gaddr));
}
__device__ __forceinline__ void cp_commit() {
    asm volatile("cp.async.commit_group;");
}
__device__ __forceinline__ void ldsm4(uint32_t r[4], uint32_t addr) {
    asm volatile("ldmatrix.sync.aligned.m8n8.x4.shared.b16 {%0,%1,%2,%3}, [%4];"
                 : "=r"(r[0]), "=r"(r[1]), "=r"(r[2]), "=r"(r[3]) : "r"(addr));
}
__device__ __forceinline__ void hmma(float c[4], const uint32_t a[4],
                                     uint32_t b0, uint32_t b1) {
    asm volatile(
        "mma.sync.aligned.m16n8k16.row.col.f32.f16.f16.f32 "
        "{%0,%1,%2,%3}, {%4,%5,%6,%7}, {%8,%9}, {%0,%1,%2,%3};"
        : "+f"(c[0]), "+f"(c[1]), "+f"(c[2]), "+f"(c[3])
        : "r"(a[0]), "r"(a[1]), "r"(a[2]), "r"(a[3]), "r"(b0), "r"(b1));
}

// ---------------- prep kernels ------------------------------------------------
__global__ void conv_x(const float* __restrict__ x) {
    int i = blockIdx.x * blockDim.x + threadIdx.x;
    int stride = gridDim.x * blockDim.x;
    const int TOT4 = (MROWS * 256) / 4;
    for (; i < TOT4; i += stride) {
        float4 v = ((const float4*)x)[i];
        __half2 h0(__float2half_rn(v.x), __float2half_rn(v.y));
        __half2 h1(__float2half_rn(v.z), __float2half_rn(v.w));
        ((uint32_t*)g_xh)[i * 2 + 0] = *(uint32_t*)&h0;
        ((uint32_t*)g_xh)[i * 2 + 1] = *(uint32_t*)&h1;
    }
}

__global__ void pack_w(const float* __restrict__ Wq, const float* __restrict__ Wkv,
                       const float* __restrict__ Wsr, const float* __restrict__ Wproj,
                       const float* __restrict__ bq, const float* __restrict__ bkv,
                       const float* __restrict__ bsr, const float* __restrict__ qe) {
    int t = blockIdx.x * blockDim.x + threadIdx.x;
    int stride = gridDim.x * blockDim.x;
    if (t < 1024)
        g_bcat[t] = (t < 256) ? (bq[t] + qe[t]) : (t < 768 ? bkv[t - 256] : bsr[t - 768]);
    const int TOT = 1024 * 256 + 256 * 256;
    for (int idx = t; idx < TOT; idx += stride) {
        float w;
        if (idx < 1024 * 256) {
            int c = idx >> 8, k = idx & 255;
            if (c < 256)      w = Wq[k * 256 + c];
            else if (c < 768) w = Wkv[k * 512 + (c - 256)];
            else              w = Wsr[k * 256 + (c - 768)];
            g_wt[idx] = __float2half_rn(w);
        } else {
            int j = idx - 1024 * 256;
            int c = j >> 8, k = j & 255;
            g_wp[j] = __float2half_rn(Wproj[k * 256 + c]);
        }
    }
}

// ---------------- HMMA fp16 single-pass GEMM: swizzled, 4-stage K=32 ---------
#define STGF 16384
#define T_B  8192
__global__ __launch_bounds__(256, 2)
void gemm_mma(const __half* __restrict__ A, const __half* __restrict__ B,
              const float* __restrict__ bias, float* __restrict__ Cout, int mode) {
    extern __shared__ __align__(128) uint8_t smem[];
    const int t = threadIdx.x, w = t >> 5, lane = t & 31;
    const int bm = blockIdx.y * 128, bn = blockIdx.x * 128;
    const int wm = (w >> 2) * 64, wn = (w & 3) * 32;
    const uint32_t sbase = s2u(smem);

    float c[4][4][4];
#pragma unroll
    for (int i = 0; i < 4; i++)
#pragma unroll
        for (int j = 0; j < 4; j++)
#pragma unroll
            for (int k = 0; k < 4; k++) c[i][j][k] = 0.f;

    uint32_t aRow[4], bRow[2];
#pragma unroll
    for (int mt = 0; mt < 4; mt++)
        aRow[mt] = (uint32_t)((wm + mt * 16 + (lane & 15)) * 64);
    {
        int nr = wn + (lane >> 4) * 8 + (lane & 7);
        bRow[0] = (uint32_t)(T_B + nr * 64);
        bRow[1] = (uint32_t)(T_B + (nr + 16) * 64);
    }
    const uint32_t aSw = (uint32_t)(((lane & 15) >> 1) & 3);
    const uint32_t bSw = (uint32_t)(((lane & 7) >> 1) & 3);
    const uint32_t cA = (uint32_t)(lane >> 4);
    const uint32_t cB = (uint32_t)((lane >> 3) & 1);

    const int r0 = t >> 2, cc = t & 3;
    const uint32_t csw = (uint32_t)((cc ^ ((r0 >> 1) & 3)) << 4);
    const size_t aG = (size_t)(bm + r0) * 256 + cc * 8;
    const size_t bG = (size_t)(bn + r0) * 256 + cc * 8;
    const uint32_t sd0 = (uint32_t)(r0 * 64) + csw;
    const uint32_t sd1 = sd0 + 64 * 64;

#define ISSUE(IT)                                                     \
    do {                                                              \
        uint32_t _so = sbase + ((IT) & 3) * STGF;                     \
        int _ko = (IT) * 32;                                          \
        cp_async16(_so + sd0,       A + aG + _ko);                    \
        cp_async16(_so + sd1,       A + aG + 64 * 256 + _ko);         \
        cp_async16(_so + T_B + sd0, B + bG + _ko);                    \
        cp_async16(_so + T_B + sd1, B + bG + 64 * 256 + _ko);         \
        cp_commit();                                                  \
    } while (0)

    ISSUE(0); ISSUE(1); ISSUE(2);

#pragma unroll 1
    for (int it = 0; it < 8; it++) {
        if (it < 6)       asm volatile("cp.async.wait_group 2;");
        else if (it == 6) asm volatile("cp.async.wait_group 1;");
        else              asm volatile("cp.async.wait_group 0;");
        __syncthreads();
        if (it + 3 < 8) ISSUE(it + 3);

        uint32_t so = sbase + (it & 3) * STGF;
#pragma unroll
        for (int ks = 0; ks < 2; ks++) {
            uint32_t swA = ((cA + 2 * ks) ^ aSw) << 4;
            uint32_t swB = ((cB + 2 * ks) ^ bSw) << 4;
            uint32_t a[4][4], b[2][4];
#pragma unroll
            for (int np = 0; np < 2; np++)
                ldsm4(b[np], so + bRow[np] + swB);
#pragma unroll
            for (int mt = 0; mt < 4; mt++) ldsm4(a[mt], so + aRow[mt] + swA);
#pragma unroll
            for (int mt = 0; mt < 4; mt++)
#pragma unroll
                for (int nt = 0; nt < 4; nt++)
                    hmma(c[mt][nt], a[mt], b[nt >> 1][(nt & 1) * 2],
                         b[nt >> 1][(nt & 1) * 2 + 1]);
        }
    }
#undef ISSUE

    const int g = lane >> 2, tq = lane & 3;
#pragma unroll
    for (int mt = 0; mt < 4; mt++) {
#pragma unroll
        for (int rs = 0; rs < 2; rs++) {
            int row = bm + wm + mt * 16 + g + rs * 8;
            int b = row / NTOK, n = row - b * NTOK;
#pragma unroll
            for (int nt = 0; nt < 4; nt++) {
                int col0 = bn + wn + nt * 8 + tq * 2;
                float v0 = c[mt][nt][rs * 2 + 0] + bias[col0];
                float v1 = c[mt][nt][rs * 2 + 1] + bias[col0 + 1];
                if (mode == 0) {
                    if (col0 < 256) {
                        int h = col0 >> 5, d = col0 & 31;
                        __half2 hv(__float2half_rn(v0), __float2half_rn(v1));
                        *(uint32_t*)(g_qh + (((size_t)b * 8 + h) * NTOK + n) * 32 + d) =
                            *(uint32_t*)&hv;
                    } else if (col0 < 768) {
                        __half2 hv(__float2half_rn(v0), __float2half_rn(v1));
                        *(uint32_t*)(g_kvh + ((size_t)b * NTOK + n) * 512 + (col0 - 256)) =
                            *(uint32_t*)&hv;
                    } else {
                        float g0 = 0.5f * v0 * (1.f + erff(v0 * 0.70710678118654752f));
                        float g1 = 0.5f * v1 * (1.f + erff(v1 * 0.70710678118654752f));
                        __half2 hv(__float2half_rn(g0), __float2half_rn(g1));
                        *(uint32_t*)(g_xsrh + ((size_t)b * NTOK + n) * 256 + (col0 - 768)) =
                            *(uint32_t*)&hv;
                    }
                } else {
                    Cout[(size_t)row * 256 + col0] = v0;
                    Cout[(size_t)row * 256 + col0 + 1] = v1;
                }
            }
        }
    }
}

// ---------------- pool (8x8 mean) + layernorm (fp16 input) --------------------
__global__ void pool_ln(const float* __restrict__ ln_g, const float* __restrict__ ln_b) {
    int bp = blockIdx.x;
    int b = bp / PLP, p = bp % PLP;
    int ph = p / 7, pw = p % 7;
    int c = threadIdx.x;
    int wid = c >> 5, lane = c & 31;
    float s = 0.f;
    const __half* base = g_xsrh + (size_t)b * NTOK * 256 + c;
#pragma unroll
    for (int ii = 0; ii < 8; ii++)
#pragma unroll
        for (int jj = 0; jj < 8; jj++)
            s += __half2float(base[(size_t)((ph * 8 + ii) * 56 + pw * 8 + jj) * 256]);
    s *= (1.f / 64.f);

    __shared__ float wred[8];
    __shared__ float stat[2];
    float v = s;
#pragma unroll
    for (int o = 16; o; o >>= 1) v += __shfl_xor_sync(0xffffffffu, v, o);
    if (lane == 0) wred[wid] = v;
    __syncthreads();
    if (c == 0) {
        float tot = 0.f;
#pragma unroll
        for (int u = 0; u < 8; u++) tot += wred[u];
        stat[0] = tot * (1.f / 256.f);
    }
    __syncthreads();
    float mu = stat[0];
    float d = s - mu;
    v = d * d;
#pragma unroll
    for (int o = 16; o; o >>= 1) v += __shfl_xor_sync(0xffffffffu, v, o);
    if (lane == 0) wred[wid] = v;
    __syncthreads();
    if (c == 0) {
        float tot = 0.f;
#pragma unroll
        for (int u = 0; u < 8; u++) tot += wred[u];
        stat[1] = tot * (1.f / 256.f);
    }
    __syncthreads();
    float var = stat[1];
    g_xp[(size_t)bp * 256 + c] = d * rsqrtf(var + 1e-5f) * ln_g[c] + ln_b[c];
}

// ---------------- small kvp GEMM (392 x 512 x 256), half2 output -------------
__global__ __launch_bounds__(256)
void kvp_gemm(const float* __restrict__ Wkv, const float* __restrict__ bkv) {
    __shared__ float sx[4][256];
    int t = threadIdx.x;
    int r0 = blockIdx.x * 4;
#pragma unroll
    for (int r = 0; r < 4; r++) sx[r][t] = g_xp[(size_t)(r0 + r) * 256 + t];
    __syncthreads();
    int c0 = t * 2;
    float a0[4], a1[4];
#pragma unroll
    for (int r = 0; r < 4; r++) { a0[r] = 0.f; a1[r] = 0.f; }
#pragma unroll 4
    for (int k = 0; k < 256; k++) {
        float2 w = *(const float2*)(Wkv + (size_t)k * 512 + c0);
#pragma unroll
        for (int r = 0; r < 4; r++) {
            float xv = sx[r][k];
            a0[r] = fmaf(xv, w.x, a0[r]);
            a1[r] = fmaf(xv, w.y, a1[r]);
        }
    }
    float b0 = bkv[c0], b1 = bkv[c0 + 1];
#pragma unroll
    for (int r = 0; r < 4; r++) {
        __half2 hv(__float2half_rn(a0[r] + b0), __float2half_rn(a1[r] + b1));
        *(uint32_t*)(g_kvph + (size_t)(r0 + r) * 512 + c0) = *(uint32_t*)&hv;
    }
}

// ---------------- attention v5: fp16 K/V/q ------------------------------------
#define SK_OFF   0
#define SV_OFF   22336
#define SKP_OFF  44672
#define SVP_OFF  47808
#define SLT_OFF  50944
#define SB_OFF   52096
#define ATTN_SMEM_BYTES 52384

__global__ __launch_bounds__(256, 2)
void attn5(const float* __restrict__ pbp, const float* __restrict__ pbl,
           const float* __restrict__ LT, const float* __restrict__ lb) {
    extern __shared__ __align__(128) uint8_t smraw[];
    __half2* sk  = (__half2*)(smraw + SK_OFF);
    __half2* sv  = (__half2*)(smraw + SV_OFF);
    __half2* skp = (__half2*)(smraw + SKP_OFF);
    __half2* svp = (__half2*)(smraw + SVP_OFF);
    float*   sLT = (float*)(smraw + SLT_OFF);
    float*   sb  = (float*)(smraw + SB_OFF);

    const int t = threadIdx.x, w = t >> 5, lane = t & 31;
    const int h  = blockIdx.y;
    const int b  = blockIdx.z;
    const int i0 = blockIdx.x * 4;

    {
        float4* z = (float4*)sv;
        for (int idx = t; idx < 1396; idx += 256)
            z[idx] = make_float4(0.f, 0.f, 0.f, 0.f);
    }
    if (t < 49)       sb[t] = pbp[h * 49 + t];
    else if (t < 58)  sb[t] = pbl[h * 9 + (t - 49)];
    else if (t < 67)  sb[t] = lb[h * 9 + (t - 58)];
    __syncthreads();

    for (int tok = t; tok < 336; tok += 256) {
        int ri = tok / 56, cc = tok - ri * 56;
        int gr = i0 - 1 + ri;
        if ((unsigned)gr < 56u) {
            int n = gr * 56 + cc;
            const uint4* kg = (const uint4*)(g_kvh + ((size_t)(b * NTOK + n) * 512 + h * 32));
            int sbs = ri * 58 + cc + 1;
#pragma unroll
            for (int u = 0; u < 4; u++) {
                uint4 kk = kg[u];
                uint4 vv = kg[32 + u];
                const uint32_t* kw = (const uint32_t*)&kk;
                const uint32_t* vw = (const uint32_t*)&vv;
#pragma unroll
                for (int q2 = 0; q2 < 4; q2++) {
                    ((uint32_t*)sk)[(4 * u + q2) * 349 + sbs] = kw[q2];
                    ((uint32_t*)sv)[(4 * u + q2) * 349 + sbs] = vw[q2];
                }
            }
        }
    }
    for (int idx = t; idx < 49 * 4; idx += 256) {
        int p = idx >> 2, u = idx & 3;
        const uint4* src = (const uint4*)(g_kvph + ((size_t)(b * PLP + p) * 512 + h * 32));
        ((uint4*)(skp + p * 16))[u] = src[u];
        ((uint4*)(svp + p * 16))[u] = src[32 + u];
    }
    for (int idx = t; idx < 288; idx += 256) {
        int d = idx / 9, l = idx - d * 9;
        sLT[l * 32 + d] = LT[(h * 32 + d) * 9 + l];
    }
    __syncthreads();

    const int rp2 = w >> 2;
    const int jt  = w & 3;
    const int jj  = lane >> 1;
    const int dh  = lane & 1;
    const bool act = jj < 14;
    const int j  = jt * 14 + (act ? jj : 0);
    const int iA = i0 + rp2 * 2;
    const int nA = iA * 56 + j;
    const int dbase = dh * 16;
    const int dpb = dh * 8;

    float qA[16], qB[16];
    {
        const uint4* qsA = (const uint4*)(g_qh + ((((size_t)b * 8 + h) * NTOK + nA) * 32 + dbase));
        const uint4* qsB = (const uint4*)(g_qh + ((((size_t)b * 8 + h) * NTOK + nA + 56) * 32 + dbase));
#pragma unroll
        for (int u = 0; u < 2; u++) {
            uint4 ra = qsA[u], rb = qsB[u];
            const __half2* ha = (const __half2*)&ra;
            const __half2* hb = (const __half2*)&rb;
#pragma unroll
            for (int q2 = 0; q2 < 4; q2++) {
                float2 fa = __half22float2(ha[q2]);
                float2 fb = __half22float2(hb[q2]);
                qA[u * 8 + q2 * 2 + 0] = fa.x; qA[u * 8 + q2 * 2 + 1] = fa.y;
                qB[u * 8 + q2 * 2 + 0] = fb.x; qB[u * 8 + q2 * 2 + 1] = fb.y;
            }
        }
    }

    float eA9[9], eB9[9];
    float SA = 0.f, SB = 0.f;

#pragma unroll
    for (int l = 0; l < 9; l++) {
        int di = l / 3, dj = l - di * 3;
        int sA = (rp2 * 2 + di) * 58 + j + dj;
        int sB = sA + 58;
        float dA = 0.f, dB = 0.f;
#pragma unroll
        for (int dp = 0; dp < 8; dp++) {
            float2 fA = __half22float2(sk[(dpb + dp) * 349 + sA]);
            float2 fB = __half22float2(sk[(dpb + dp) * 349 + sB]);
            dA = fmaf(qA[2 * dp], fA.x, dA); dA = fmaf(qA[2 * dp + 1], fA.y, dA);
            dB = fmaf(qB[2 * dp], fB.x, dB); dB = fmaf(qB[2 * dp + 1], fB.y, dB);
        }
        dA += __shfl_xor_sync(0xffffffffu, dA, 1);
        dB += __shfl_xor_sync(0xffffffffu, dB, 1);
        bool vA = act && ((unsigned)(iA + di - 1) < 56u) && ((unsigned)(j + dj - 1) < 56u);
        bool vB = act && ((unsigned)(iA + di) < 56u) && ((unsigned)(j + dj - 1) < 56u);
        float eA = vA ? __expf(dA * ASCALE + sb[49 + l]) : 0.f;
        float eB = vB ? __expf(dB * ASCALE + sb[49 + l]) : 0.f;
        eA9[l] = eA; eB9[l] = eB;
        SA += eA; SB += eB;
    }

    float oA[16], oB[16];
#pragma unroll
    for (int d = 0; d < 16; d++) { oA[d] = 0.f; oB[d] = 0.f; }
#pragma unroll 7
    for (int p = 0; p < 49; p++) {
        const uint4* kp = (const uint4*)(skp + p * 16 + dpb);
        uint4 k0 = kp[0], k1 = kp[1];
        const __half2* kh0 = (const __half2*)&k0;
        const __half2* kh1 = (const __half2*)&k1;
        float dA = 0.f, dB = 0.f;
#pragma unroll
        for (int u = 0; u < 4; u++) {
            float2 f0 = __half22float2(kh0[u]);
            float2 f1 = __half22float2(kh1[u]);
            dA = fmaf(qA[2 * u], f0.x, dA); dA = fmaf(qA[2 * u + 1], f0.y, dA);
            dA = fmaf(qA[8 + 2 * u], f1.x, dA); dA = fmaf(qA[9 + 2 * u], f1.y, dA);
            dB = fmaf(qB[2 * u], f0.x, dB); dB = fmaf(qB[2 * u + 1], f0.y, dB);
            dB = fmaf(qB[8 + 2 * u], f1.x, dB); dB = fmaf(qB[9 + 2 * u], f1.y, dB);
        }
        dA += __shfl_xor_sync(0xffffffffu, dA, 1);
        dB += __shfl_xor_sync(0xffffffffu, dB, 1);
        float eA = __expf(dA * ASCALE + sb[p]);
        float eB = __expf(dB * ASCALE + sb[p]);
        SA += eA; SB += eB;
        const uint4* vp = (const uint4*)(svp + p * 16 + dpb);
        uint4 v0 = vp[0], v1 = vp[1];
        const __half2* vh0 = (const __half2*)&v0;
        const __half2* vh1 = (const __half2*)&v1;
#pragma unroll
        for (int u = 0; u < 4; u++) {
            float2 f0 = __half22float2(vh0[u]);
            float2 f1 = __half22float2(vh1[u]);
            oA[2 * u]     = fmaf(eA, f0.x, oA[2 * u]);
            oA[2 * u + 1] = fmaf(eA, f0.y, oA[2 * u + 1]);
            oA[8 + 2 * u] = fmaf(eA, f1.x, oA[8 + 2 * u]);
            oA[9 + 2 * u] = fmaf(eA, f1.y, oA[9 + 2 * u]);
            oB[2 * u]     = fmaf(eB, f0.x, oB[2 * u]);
            oB[2 * u + 1] = fmaf(eB, f0.y, oB[2 * u + 1]);
            oB[8 + 2 * u] = fmaf(eB, f1.x, oB[8 + 2 * u]);
            oB[9 + 2 * u] = fmaf(eB, f1.y, oB[9 + 2 * u]);
        }
    }

    float invA = 1.f / SA, invB = 1.f / SB;
#pragma unroll
    for (int d = 0; d < 16; d++) { oA[d] *= invA; oB[d] *= invB; }

#pragma unroll
    for (int l = 0; l < 9; l++) {
        int di = l / 3, dj = l - di * 3;
        int sA = (rp2 * 2 + di) * 58 + j + dj;
        int sB = sA + 58;
        const float4* lt4 = (const float4*)(sLT + l * 32 + dbase);
        float ltA = 0.f, ltB = 0.f;
#pragma unroll
        for (int u = 0; u < 4; u++) {
            float4 kk = lt4[u];
            ltA = fmaf(qA[u * 4 + 0], kk.x, ltA); ltA = fmaf(qA[u * 4 + 1], kk.y, ltA);
            ltA = fmaf(qA[u * 4 + 2], kk.z, ltA); ltA = fmaf(qA[u * 4 + 3], kk.w, ltA);
            ltB = fmaf(qB[u * 4 + 0], kk.x, ltB); ltB = fmaf(qB[u * 4 + 1], kk.y, ltB);
            ltB = fmaf(qB[u * 4 + 2], kk.z, ltB); ltB = fmaf(qB[u * 4 + 3], kk.w, ltB);
        }
        ltA += __shfl_xor_sync(0xffffffffu, ltA, 1);
        ltB += __shfl_xor_sync(0xffffffffu, ltB, 1);
        float wA = fmaf(eA9[l], invA, ltA + sb[58 + l]);
        float wB = fmaf(eB9[l], invB, ltB + sb[58 + l]);
#pragma unroll
        for (int dp = 0; dp < 8; dp++) {
            float2 fA = __half22float2(sv[(dpb + dp) * 349 + sA]);
            float2 fB = __half22float2(sv[(dpb + dp) * 349 + sB]);
            oA[2 * dp]     = fmaf(wA, fA.x, oA[2 * dp]);
            oA[2 * dp + 1] = fmaf(wA, fA.y, oA[2 * dp + 1]);
            oB[2 * dp]     = fmaf(wB, fB.x, oB[2 * dp]);
            oB[2 * dp + 1] = fmaf(wB, fB.y, oB[2 * dp + 1]);
        }
    }

    if (act) {
        size_t baseA = ((size_t)b * NTOK + nA) * 256 + h * 32 + dbase;
        size_t baseB = baseA + (size_t)56 * 256;
        uint32_t* ohA = (uint32_t*)(g_oh + baseA);
        uint32_t* ohB = (uint32_t*)(g_oh + baseB);
#pragma unroll
        for (int d2 = 0; d2 < 8; d2++) {
            __half2 hA(__float2half_rn(oA[d2 * 2]), __float2half_rn(oA[d2 * 2 + 1]));
            __half2 hB(__float2half_rn(oB[d2 * 2]), __float2half_rn(oB[d2 * 2 + 1]));
            ohA[d2] = *(uint32_t*)&hA;
            ohB[d2] = *(uint32_t*)&hB;
        }
    }
}

// ---------------- launch -------------------------------------------------------
extern "C" void kernel_launch(void* const* d_in, const int* in_sizes, int n_in,
                              void* d_out, int out_size) {
    (void)in_sizes; (void)n_in; (void)out_size;
    const float* x     = (const float*)d_in[0];
    const float* Wq    = (const float*)d_in[1];
    const float* bq    = (const float*)d_in[2];
    const float* Wkv   = (const float*)d_in[3];
    const float* bkv   = (const float*)d_in[4];
    const float* qe    = (const float*)d_in[5];
    const float* Wsr   = (const float*)d_in[6];
    const float* bsr   = (const float*)d_in[7];
    const float* ln_g  = (const float*)d_in[8];
    const float* ln_b  = (const float*)d_in[9];
    const float* pbp   = (const float*)d_in[10];
    const float* pbl   = (const float*)d_in[11];
    const float* LT    = (const float*)d_in[12];
    const float* lb    = (const float*)d_in[13];
    const float* Wproj = (const float*)d_in[14];
    const float* bproj = (const float*)d_in[15];
    float* out = (float*)d_out;

    __half *pxh, *pwt, *pwp, *poh;
    float* pbcat;
    cudaGetSymbolAddress((void**)&pxh, g_xh);
    cudaGetSymbolAddress((void**)&pwt, g_wt);
    cudaGetSymbolAddress((void**)&pwp, g_wp);
    cudaGetSymbolAddress((void**)&poh, g_oh);
    cudaGetSymbolAddress((void**)&pbcat, g_bcat);

    cudaFuncSetAttribute(gemm_mma, cudaFuncAttributeMaxDynamicSharedMemorySize, 4 * STGF);
    cudaFuncSetAttribute(attn5, cudaFuncAttributeMaxDynamicSharedMemorySize,
                         ATTN_SMEM_BYTES);

    conv_x<<<2048, 256>>>(x);
    pack_w<<<320, 256>>>(Wq, Wkv, Wsr, Wproj, bq, bkv, bsr, qe);

    // fused q/kv/xsr GEMM: 25088 x 1024 x 256 (fp16 single pass)
    gemm_mma<<<dim3(8, 196), 256, 4 * STGF>>>(pxh, pwt, pbcat, nullptr, 0);

    pool_ln<<<BATCH * PLP, 256>>>(ln_g, ln_b);
    kvp_gemm<<<98, 256>>>(Wkv, bkv);

    attn5<<<dim3(14, 8, 8), 256, ATTN_SMEM_BYTES>>>(pbp, pbl, LT, lb);

    // projection GEMM: 25088 x 256 x 256 -> d_out (fp16 single pass)
    gemm_mma<<<dim3(2, 196), 256, 4 * STGF>>>(poh, pwp, bproj, out, 1);
}